// round 11
// baseline (speedup 1.0000x reference)
#include <cuda_runtime.h>
#include <cuda_fp16.h>
#include <math.h>
#include <stdint.h>

#define Bb 4
#define Tt 4096
#define Ee 1024
#define Hh 16
#define Dd 64
#define M_ROWS (Bb*Tt)          // 16384
#define FF (4*Ee)               // 4096
#define PIO2 1.5707963267948966f

// ===================== PTX helpers (baseline ISA only) =====================
__device__ __forceinline__ uint32_t smem_to_u32(const void* p) {
    uint32_t a;
    asm("{ .reg .u64 t; cvta.to.shared.u64 t, %1; cvt.u32.u64 %0, t; }" : "=r"(a) : "l"(p));
    return a;
}
#define CP_ASYNC16(saddr, gptr) \
    asm volatile("cp.async.cg.shared.global [%0], [%1], 16;" :: "r"(saddr), "l"(gptr))
#define CP_COMMIT() asm volatile("cp.async.commit_group;" ::: "memory")
#define CP_WAIT1()  asm volatile("cp.async.wait_group 1;" ::: "memory")

#define LDSM_X4(r0,r1,r2,r3, addr) \
    asm volatile("ldmatrix.sync.aligned.m8n8.x4.shared.b16 {%0,%1,%2,%3}, [%4];" \
        : "=r"(r0),"=r"(r1),"=r"(r2),"=r"(r3) : "r"(addr))

#define MMA_F16(d, a, b) \
    asm volatile("mma.sync.aligned.m16n8k16.row.col.f32.f16.f16.f32 " \
        "{%0,%1,%2,%3}, {%4,%5,%6,%7}, {%8,%9}, {%0,%1,%2,%3};" \
        : "+f"((d)[0]),"+f"((d)[1]),"+f"((d)[2]),"+f"((d)[3]) \
        : "r"((a)[0]),"r"((a)[1]),"r"((a)[2]),"r"((a)[3]), "r"((b)[0]),"r"((b)[1]))

__device__ __forceinline__ uint32_t pack_h2(float a, float b) {
    __half2 h = __floats2half2_rn(a, b);
    return *(uint32_t*)&h;
}

// ===================== scratch (device globals) =====================
__device__ __half g_h   [M_ROWS*Ee];           // LN out (fp16)
__device__ __half g_attn[M_ROWS*Ee];           // attn out (fp16)
__device__ __half g_fc  [(size_t)M_ROWS*FF];   // gelu out (fp16)
__device__ __half g_q [M_ROWS*Ee];
__device__ __half g_k [M_ROWS*Ee];
__device__ __half g_v [M_ROWS*Ee];
__device__ float g_x2[M_ROWS*Ee];
__device__ float g_kv  [Bb*Hh*128*Dd];
__device__ float g_ksum[Bb*Hh*128];
// transposed fp16 weights: [N, K]
__device__ __half g_wqkv[3*Ee*Ee];             // q|k|v stacked in N
__device__ __half g_wo  [Ee*Ee];
__device__ __half g_wfc [(size_t)FF*Ee];
__device__ __half g_wpj [(size_t)Ee*FF];

// ===================== transpose + fp16: W[K,N] -> T[N,K] ============
__global__ void transpose_h_kernel(const float* __restrict__ W,
                                   __half* __restrict__ T, int K, int N) {
    __shared__ float ts[32][33];
    int n0 = blockIdx.x * 32, k0 = blockIdx.y * 32;
    int tx = threadIdx.x & 31, ty = threadIdx.x >> 5;
#pragma unroll
    for (int i = 0; i < 32; i += 8)
        ts[ty + i][tx] = W[(size_t)(k0 + ty + i) * N + n0 + tx];
    __syncthreads();
#pragma unroll
    for (int i = 0; i < 32; i += 8)
        T[(size_t)(n0 + ty + i) * K + k0 + tx] = __float2half_rn(ts[tx][ty + i]);
}

// all three QKV weights in one launch (blockIdx.z selects)
__global__ void transpose_qkv_kernel(const float* __restrict__ wq,
                                     const float* __restrict__ wk,
                                     const float* __restrict__ wv,
                                     __half* __restrict__ T) {
    __shared__ float ts[32][33];
    const float* W = blockIdx.z == 0 ? wq : (blockIdx.z == 1 ? wk : wv);
    __half* Tz = T + (size_t)blockIdx.z * Ee * Ee;
    int n0 = blockIdx.x * 32, k0 = blockIdx.y * 32;
    int tx = threadIdx.x & 31, ty = threadIdx.x >> 5;
#pragma unroll
    for (int i = 0; i < 32; i += 8)
        ts[ty + i][tx] = W[(size_t)(k0 + ty + i) * Ee + n0 + tx];
    __syncthreads();
#pragma unroll
    for (int i = 0; i < 32; i += 8)
        Tz[(size_t)(n0 + ty + i) * Ee + k0 + tx] = __float2half_rn(ts[tx][ty + i]);
}

// ===================== LayerNorm -> fp16 =====================
__global__ void ln_kernel(const float* __restrict__ X, const float* __restrict__ w,
                          const float* __restrict__ b, __half* __restrict__ Y) {
    int row = blockIdx.x;
    int tid = threadIdx.x;                 // 256 threads
    const float4* x4 = (const float4*)(X + (size_t)row * Ee);
    float4 v = x4[tid];
    __shared__ float red[8];

    float s = v.x + v.y + v.z + v.w;
    for (int o = 16; o > 0; o >>= 1) s += __shfl_down_sync(0xffffffffu, s, o);
    if ((tid & 31) == 0) red[tid >> 5] = s;
    __syncthreads();
    if (tid < 8) {
        float t = red[tid];
        for (int o = 4; o > 0; o >>= 1) t += __shfl_down_sync(0xffu, t, o);
        if (tid == 0) red[0] = t;
    }
    __syncthreads();
    float mu = red[0] * (1.0f / Ee);
    __syncthreads();

    float dx = v.x - mu, dy = v.y - mu, dz = v.z - mu, dw = v.w - mu;
    float ss = dx*dx + dy*dy + dz*dz + dw*dw;
    for (int o = 16; o > 0; o >>= 1) ss += __shfl_down_sync(0xffffffffu, ss, o);
    if ((tid & 31) == 0) red[tid >> 5] = ss;
    __syncthreads();
    if (tid < 8) {
        float t = red[tid];
        for (int o = 4; o > 0; o >>= 1) t += __shfl_down_sync(0xffu, t, o);
        if (tid == 0) red[0] = t;
    }
    __syncthreads();
    float rstd = rsqrtf(red[0] * (1.0f / Ee) + 1e-5f);

    float4 wv = ((const float4*)w)[tid];
    float4 bv = ((const float4*)b)[tid];
    uint32_t h0 = pack_h2(dx * rstd * wv.x + bv.x, dy * rstd * wv.y + bv.y);
    uint32_t h1 = pack_h2(dz * rstd * wv.z + bv.z, dw * rstd * wv.w + bv.w);
    *(uint2*)&Y[(size_t)row * Ee + tid * 4] = make_uint2(h0, h1);
}

// ===================== fp16 mma.sync GEMM ==================================
// C[m,n] = act( A[m,:] @ Bt[n,:]^T + bias[n] ) (+ res)
// Tile 128x128, K-chunk 64, 3-stage cp.async, 8 warps, 2 CTAs/SM,
// fragment double-buffering (LDSM for ks+1 issued before MMAs of ks).
// ACT: 0 none (fp32 out+res), 2 gelu (fp16 out), 3 fused-QKV (fp16 out x3, relu sec<2).
#define STAGE_BYTES 32768
#define GT_SMEM (3*STAGE_BYTES)  // 96KB -> 2 CTAs/SM

__device__ __forceinline__ void load_stage(
    uint32_t sbase, int slot, int tid, int m0, int n0, int k0, int K,
    const __half* A, const __half* B)
{
    uint32_t sb = sbase + slot * STAGE_BYTES;
#pragma unroll
    for (int i = 0; i < 4; i++) {
        int u = tid + i * 256;        // 0..1023: 128 rows x 8 16B-chunks
        int r = u >> 3, c = u & 7;
        uint32_t soff = (uint32_t)(r * 128) + (uint32_t)(((c ^ (r & 7)) << 4));
        CP_ASYNC16(sb + soff, A + (size_t)(m0 + r) * K + k0 + c * 8);
    }
#pragma unroll
    for (int i = 0; i < 4; i++) {
        int u = tid + i * 256;
        int r = u >> 3, c = u & 7;
        uint32_t soff = (uint32_t)(r * 128) + (uint32_t)(((c ^ (r & 7)) << 4));
        CP_ASYNC16(sb + 16384 + soff, B + (size_t)(n0 + r) * K + k0 + c * 8);
    }
}

template<int ACT, bool RES>
__global__ __launch_bounds__(256, 2) void gemm_h(
    const __half* __restrict__ A, const __half* __restrict__ Bt,
    const float* __restrict__ bias, const float* __restrict__ bias2,
    const float* __restrict__ bias3, const float* __restrict__ res,
    float* __restrict__ Cf,
    __half* __restrict__ Ch, __half* __restrict__ Ch2, __half* __restrict__ Ch3,
    int M, int N, int K)
{
    extern __shared__ char smem[];
    uint32_t sbase = smem_to_u32(smem);
    int tid = threadIdx.x;
    int wid = tid >> 5, l = tid & 31;
    int warpM = wid >> 2, warpN = wid & 3;     // 2 x 4 warps, warp tile 64x32
    int m0 = blockIdx.y * 128, n0 = blockIdx.x * 128;

    int g = l & 7, grp = l >> 3;
    uint32_t constA = (uint32_t)((warpM * 64 + (grp & 1) * 8 + g) * 128);
    int khA = grp >> 1;
    uint32_t constB = (uint32_t)((warpN * 32 + (grp >> 1) * 8 + g) * 128);
    int khB = grp & 1;

    float acc[4][4][4];
#pragma unroll
    for (int mi = 0; mi < 4; mi++)
#pragma unroll
        for (int ni = 0; ni < 4; ni++)
#pragma unroll
            for (int j = 0; j < 4; j++) acc[mi][ni][j] = 0.0f;

    const int NC = K >> 6;                 // K-chunk 64
    load_stage(sbase, 0, tid, m0, n0, 0, K, A, Bt);
    CP_COMMIT();
    load_stage(sbase, 1, tid, m0, n0, 64, K, A, Bt);
    CP_COMMIT();

    uint32_t Af[2][4][4], Bf[2][4][2];

    int slot = 0, nslot = 2;
    for (int c = 0; c < NC; c++) {
        CP_WAIT1();
        __syncthreads();
        if (c + 2 < NC)
            load_stage(sbase, nslot, tid, m0, n0, (c + 2) * 64, K, A, Bt);
        CP_COMMIT();
        uint32_t sA = sbase + slot * STAGE_BYTES;
        uint32_t sB = sA + 16384;

        // prologue: fragments for ks=0
        {
            uint32_t segA = (uint32_t)((khA ^ g) << 4);
            uint32_t segB = (uint32_t)((khB ^ g) << 4);
#pragma unroll
            for (int mi = 0; mi < 4; mi++) {
                uint32_t ad = sA + constA + mi * 2048 + segA;
                LDSM_X4(Af[0][mi][0], Af[0][mi][1], Af[0][mi][2], Af[0][mi][3], ad);
            }
#pragma unroll
            for (int np = 0; np < 2; np++) {
                uint32_t bd = sB + constB + np * 2048 + segB;
                uint32_t t0, t1, t2, t3;
                LDSM_X4(t0, t1, t2, t3, bd);
                Bf[0][np*2][0] = t0; Bf[0][np*2][1] = t1;
                Bf[0][np*2+1][0] = t2; Bf[0][np*2+1][1] = t3;
            }
        }
#pragma unroll
        for (int ks = 0; ks < 4; ks++) {
            int cur = ks & 1, nxt = cur ^ 1;
            if (ks < 3) {   // prefetch fragments for ks+1 BEFORE computing ks
                uint32_t segA = (uint32_t)((((ks + 1) * 2 + khA) ^ g) << 4);
                uint32_t segB = (uint32_t)((((ks + 1) * 2 + khB) ^ g) << 4);
#pragma unroll
                for (int mi = 0; mi < 4; mi++) {
                    uint32_t ad = sA + constA + mi * 2048 + segA;
                    LDSM_X4(Af[nxt][mi][0], Af[nxt][mi][1], Af[nxt][mi][2], Af[nxt][mi][3], ad);
                }
#pragma unroll
                for (int np = 0; np < 2; np++) {
                    uint32_t bd = sB + constB + np * 2048 + segB;
                    uint32_t t0, t1, t2, t3;
                    LDSM_X4(t0, t1, t2, t3, bd);
                    Bf[nxt][np*2][0] = t0; Bf[nxt][np*2][1] = t1;
                    Bf[nxt][np*2+1][0] = t2; Bf[nxt][np*2+1][1] = t3;
                }
            }
#pragma unroll
            for (int mi = 0; mi < 4; mi++)
#pragma unroll
                for (int ni = 0; ni < 4; ni++)
                    MMA_F16(acc[mi][ni], Af[cur][mi], Bf[cur][ni]);
        }
        slot = slot == 2 ? 0 : slot + 1;
        nslot = nslot == 2 ? 0 : nslot + 1;
    }

    // ---------------- epilogue ----------------
    int sec = n0 >> 10;                       // uniform per CTA (ACT3)
    const float* bsel = (ACT == 3) ? (sec == 0 ? bias : (sec == 1 ? bias2 : bias3)) : bias;
    __half* hsel = (ACT == 3) ? (sec == 0 ? Ch : (sec == 1 ? Ch2 : Ch3)) : Ch;
    int nsub = (ACT == 3) ? (sec << 10) : 0;
    int rowstride = (ACT == 3) ? Ee : N;
#pragma unroll
    for (int mi = 0; mi < 4; mi++) {
#pragma unroll
        for (int half_ = 0; half_ < 2; half_++) {
            int m = m0 + warpM * 64 + mi * 16 + (l >> 2) + half_ * 8;
#pragma unroll
            for (int ni = 0; ni < 4; ni++) {
                int n = n0 + warpN * 32 + ni * 8 + (l & 3) * 2;
                float v0 = acc[mi][ni][half_ * 2 + 0];
                float v1 = acc[mi][ni][half_ * 2 + 1];
                float2 bz = __ldg((const float2*)&bsel[n - nsub]);
                v0 += bz.x; v1 += bz.y;
                if (ACT == 3 && sec < 2) {
                    v0 = fmaxf(v0, 0.0f); v1 = fmaxf(v1, 0.0f);
                } else if (ACT == 2) {
                    v0 = 0.5f * v0 * (1.0f + erff(v0 * 0.70710678118654752f));
                    v1 = 0.5f * v1 * (1.0f + erff(v1 * 0.70710678118654752f));
                }
                size_t off = (size_t)m * rowstride + (n - nsub);
                if (RES) {
                    float2 rv = *(const float2*)&res[off];
                    v0 += rv.x; v1 += rv.y;
                }
                if (ACT == 0) {
                    *(float2*)&Cf[off] = make_float2(v0, v1);
                } else {
                    *(uint32_t*)&hsel[off] = pack_h2(v0, v1);
                }
            }
        }
    }
}

// ===================== zero (kv + ksum in one launch) =====================
__global__ void zero2_kernel(float* p1, int n1, float* p2, int n2) {
    int i = blockIdx.x * blockDim.x + threadIdx.x;
    if (i < n1) p1[i] = 0.0f;
    if (i < n2) p2[i] = 0.0f;
}

// ===================== kv reduction (fp16 inputs) =====================
#define TSPLIT 8
__global__ __launch_bounds__(256) void kv_kernel(
    const __half* __restrict__ Kp, const __half* __restrict__ Vp,
    float* __restrict__ kv, float* __restrict__ ksum)
{
    int bh = blockIdx.x;
    int b = bh >> 4, h = bh & 15;
    int tid = threadIdx.x;
    __shared__ float ks_sh[32][64];
    __shared__ float vs_sh[32][64];
    __shared__ float s_sh[32], c_sh[32];

    int dd = tid & 63;
    int eb = tid >> 6;
    int e0 = eb * 16;
    float acc_s[16], acc_c[16];
#pragma unroll
    for (int i = 0; i < 16; i++) { acc_s[i] = 0.0f; acc_c[i] = 0.0f; }
    float ksum_s = 0.0f, ksum_c = 0.0f;

    int rr = tid >> 3, c8 = (tid & 7) * 8;       // 256 threads -> 32 rows x 8 cols-of-8
    int tbase = blockIdx.y * (Tt / TSPLIT);
    for (int tt = 0; tt < Tt / TSPLIT; tt += 32) {
        int t0 = tbase + tt;
        {
            size_t off = (size_t)(b * Tt + t0 + rr) * Ee + h * 64 + c8;
            uint4 kk = *(const uint4*)&Kp[off];
            uint4 vv = *(const uint4*)&Vp[off];
            const __half2* kh = (const __half2*)&kk;
            const __half2* vh = (const __half2*)&vv;
#pragma unroll
            for (int j = 0; j < 4; j++) {
                float2 kf = __half22float2(kh[j]);
                float2 vf = __half22float2(vh[j]);
                ks_sh[rr][c8 + j*2 + 0] = kf.x;
                ks_sh[rr][c8 + j*2 + 1] = kf.y;
                vs_sh[rr][c8 + j*2 + 0] = vf.x;
                vs_sh[rr][c8 + j*2 + 1] = vf.y;
            }
        }
        if (tid < 32) {
            float idx = PIO2 * (float)(t0 + tid + 1) * (1.0f / Tt);
            s_sh[tid] = sinf(idx);
            c_sh[tid] = cosf(idx);
        }
        __syncthreads();
#pragma unroll 4
        for (int r = 0; r < 32; r++) {
            float kd = ks_sh[r][dd];
            float as = kd * s_sh[r];
            float ac = kd * c_sh[r];
            if (eb == 0) { ksum_s += as; ksum_c += ac; }
#pragma unroll
            for (int i = 0; i < 16; i++) {
                float ve = vs_sh[r][e0 + i];
                acc_s[i] = fmaf(as, ve, acc_s[i]);
                acc_c[i] = fmaf(ac, ve, acc_c[i]);
            }
        }
        __syncthreads();
    }
    float* kvb = kv + (size_t)bh * 128 * Dd;
#pragma unroll
    for (int i = 0; i < 16; i++) {
        atomicAdd(&kvb[dd * Dd + e0 + i], acc_s[i]);
        atomicAdd(&kvb[(64 + dd) * Dd + e0 + i], acc_c[i]);
    }
    if (eb == 0) {
        atomicAdd(&ksum[bh * 128 + dd], ksum_s);
        atomicAdd(&ksum[bh * 128 + 64 + dd], ksum_c);
    }
}

// ===================== attention (fp16 q in, fp16 out) =================
__global__ __launch_bounds__(256) void attn_kernel(
    const __half* __restrict__ Qp, const float* __restrict__ kv,
    const float* __restrict__ ksum, __half* __restrict__ Op)
{
    int bh = blockIdx.y;
    int b = bh >> 4, h = bh & 15;
    int t0 = blockIdx.x * 32;
    int tid = threadIdx.x;

    __shared__ float kv_sh[128][64];
    __shared__ float q_sh[32][65];
    __shared__ float ksum_sh[128];
    __shared__ float den_sh[32], s_sh[32], c_sh[32];

#pragma unroll
    for (int ld = 0; ld < 8; ld++) {
        int id = tid + ld * 256;
        int r = id >> 4, c4 = (id & 15) * 4;
        *(float4*)&kv_sh[r][c4] = *(const float4*)&kv[((size_t)bh * 128 + r) * Dd + c4];
    }
    {
        int rr = tid >> 3, c8 = (tid & 7) * 8;
        uint4 qq = *(const uint4*)&Qp[(size_t)(b * Tt + t0 + rr) * Ee + h * 64 + c8];
        const __half2* qh = (const __half2*)&qq;
#pragma unroll
        for (int j = 0; j < 4; j++) {
            float2 qf = __half22float2(qh[j]);
            q_sh[rr][c8 + j*2 + 0] = qf.x;
            q_sh[rr][c8 + j*2 + 1] = qf.y;
        }
    }
    if (tid < 128) ksum_sh[tid] = ksum[bh * 128 + tid];
    if (tid < 32) {
        float idx = PIO2 * (float)(t0 + tid + 1) * (1.0f / Tt);
        s_sh[tid] = sinf(idx);
        c_sh[tid] = cosf(idx);
    }
    __syncthreads();

    if (tid < 32) {
        float ds = 0.0f, dc = 0.0f;
#pragma unroll 8
        for (int d = 0; d < 64; d++) {
            float qd = q_sh[tid][d];
            ds = fmaf(qd, ksum_sh[d], ds);
            dc = fmaf(qd, ksum_sh[64 + d], dc);
        }
        den_sh[tid] = s_sh[tid] * ds + c_sh[tid] * dc;
    }
    __syncthreads();

    int tl = tid & 31;
    int eb = tid >> 5;
    int e0 = eb * 8;
    float outs[8], outc[8];
#pragma unroll
    for (int j = 0; j < 8; j++) { outs[j] = 0.0f; outc[j] = 0.0f; }

#pragma unroll 4
    for (int d = 0; d < 64; d++) {
        float qd = q_sh[tl][d];
        float4 k0 = *(const float4*)&kv_sh[d][e0];
        float4 k1 = *(const float4*)&kv_sh[d][e0 + 4];
        float4 m0 = *(const float4*)&kv_sh[64 + d][e0];
        float4 m1 = *(const float4*)&kv_sh[64 + d][e0 + 4];
        outs[0]=fmaf(qd,k0.x,outs[0]); outs[1]=fmaf(qd,k0.y,outs[1]);
        outs[2]=fmaf(qd,k0.z,outs[2]); outs[3]=fmaf(qd,k0.w,outs[3]);
        outs[4]=fmaf(qd,k1.x,outs[4]); outs[5]=fmaf(qd,k1.y,outs[5]);
        outs[6]=fmaf(qd,k1.z,outs[6]); outs[7]=fmaf(qd,k1.w,outs[7]);
        outc[0]=fmaf(qd,m0.x,outc[0]); outc[1]=fmaf(qd,m0.y,outc[1]);
        outc[2]=fmaf(qd,m0.z,outc[2]); outc[3]=fmaf(qd,m0.w,outc[3]);
        outc[4]=fmaf(qd,m1.x,outc[4]); outc[5]=fmaf(qd,m1.y,outc[5]);
        outc[6]=fmaf(qd,m1.z,outc[6]); outc[7]=fmaf(qd,m1.w,outc[7]);
    }
    float z = 1.0f / fmaxf(den_sh[tl], 1e-6f);
    float s = s_sh[tl] * z, c = c_sh[tl] * z;
    uint32_t hp[4];
#pragma unroll
    for (int j = 0; j < 8; j += 2)
        hp[j >> 1] = pack_h2(s * outs[j] + c * outc[j], s * outs[j+1] + c * outc[j+1]);
    size_t off = (size_t)(b * Tt + t0 + tl) * Ee + h * 64 + e0;
    *(uint4*)&Op[off] = make_uint4(hp[0], hp[1], hp[2], hp[3]);
}

// ===================== launch =====================
extern "C" void kernel_launch(void* const* d_in, const int* in_sizes, int n_in,
                              void* d_out, int out_size) {
    const float* x      = (const float*)d_in[0];
    const float* ln1_w  = (const float*)d_in[1];
    const float* ln1_b  = (const float*)d_in[2];
    const float* wq     = (const float*)d_in[3];
    const float* bq     = (const float*)d_in[4];
    const float* wk     = (const float*)d_in[5];
    const float* bk     = (const float*)d_in[6];
    const float* wv     = (const float*)d_in[7];
    const float* bv     = (const float*)d_in[8];
    const float* wo     = (const float*)d_in[9];
    const float* bo     = (const float*)d_in[10];
    const float* ln2_w  = (const float*)d_in[11];
    const float* ln2_b  = (const float*)d_in[12];
    const float* w_fc   = (const float*)d_in[13];
    const float* b_fc   = (const float*)d_in[14];
    const float* w_proj = (const float*)d_in[15];
    const float* b_proj = (const float*)d_in[16];
    float* out = (float*)d_out;

    __half *p_h, *p_attn, *p_fc, *p_q, *p_k, *p_v;
    __half *p_wqkv, *p_wo, *p_wfc, *p_wpj;
    float *p_x2, *p_kv, *p_ksum;
    cudaGetSymbolAddress((void**)&p_h,    g_h);
    cudaGetSymbolAddress((void**)&p_attn, g_attn);
    cudaGetSymbolAddress((void**)&p_fc,   g_fc);
    cudaGetSymbolAddress((void**)&p_q,    g_q);
    cudaGetSymbolAddress((void**)&p_k,    g_k);
    cudaGetSymbolAddress((void**)&p_v,    g_v);
    cudaGetSymbolAddress((void**)&p_x2,   g_x2);
    cudaGetSymbolAddress((void**)&p_kv,   g_kv);
    cudaGetSymbolAddress((void**)&p_ksum, g_ksum);
    cudaGetSymbolAddress((void**)&p_wqkv, g_wqkv);
    cudaGetSymbolAddress((void**)&p_wo,   g_wo);
    cudaGetSymbolAddress((void**)&p_wfc,  g_wfc);
    cudaGetSymbolAddress((void**)&p_wpj,  g_wpj);

    cudaFuncSetAttribute(gemm_h<3, false>, cudaFuncAttributeMaxDynamicSharedMemorySize, GT_SMEM);
    cudaFuncSetAttribute(gemm_h<0, true>,  cudaFuncAttributeMaxDynamicSharedMemorySize, GT_SMEM);
    cudaFuncSetAttribute(gemm_h<2, false>, cudaFuncAttributeMaxDynamicSharedMemorySize, GT_SMEM);

    // launch 0: h = LN1(x)
    ln_kernel<<<M_ROWS, 256>>>(x, ln1_w, ln1_b, p_h);
    // launch 1: QKV weight transpose (all 3 in one launch)
    transpose_qkv_kernel<<<dim3(Ee/32, Ee/32, 3), 256>>>(wq, wk, wv, p_wqkv);
    // launch 2: wo transpose
    transpose_h_kernel<<<dim3(Ee/32, Ee/32), 256>>>(wo, p_wo, Ee, Ee);
    // launch 3 (ncu capture target): fused QKV GEMM, N=3072, fp16 outputs
    dim3 gqkv(3*Ee / 128, M_ROWS / 128);
    gemm_h<3, false><<<gqkv, 256, GT_SMEM>>>(p_h, p_wqkv,
        bq, bk, bv, nullptr, nullptr, p_q, p_k, p_v, M_ROWS, 3*Ee, Ee);

    // kv / ksum reduction
    zero2_kernel<<<(Bb*Hh*128*Dd + 255) / 256, 256>>>(p_kv, Bb*Hh*128*Dd, p_ksum, Bb*Hh*128);
    kv_kernel<<<dim3(Bb * Hh, TSPLIT), 256>>>(p_k, p_v, p_kv, p_ksum);

    // attention output (fp16)
    attn_kernel<<<dim3(Tt / 32, Bb * Hh), 256>>>(p_q, p_kv, p_ksum, p_attn);

    // x2 = x + attn @ wo + bo
    dim3 g1(Ee / 128, M_ROWS / 128);
    gemm_h<0, true><<<g1, 256, GT_SMEM>>>(p_attn, p_wo,
        bo, nullptr, nullptr, x, p_x2, nullptr, nullptr, nullptr, M_ROWS, Ee, Ee);

    // h = LN2(x2)
    ln_kernel<<<M_ROWS, 256>>>(p_x2, ln2_w, ln2_b, p_h);

    // fc = gelu(h @ w_fc + b_fc)  (fp16 out)
    transpose_h_kernel<<<dim3(FF/32, Ee/32), 256>>>(w_fc, p_wfc, Ee, FF);
    dim3 g2(FF / 128, M_ROWS / 128);
    gemm_h<2, false><<<g2, 256, GT_SMEM>>>(p_h, p_wfc,
        b_fc, nullptr, nullptr, nullptr, nullptr, p_fc, nullptr, nullptr, M_ROWS, FF, Ee);

    // out = x2 + fc @ w_proj + b_proj
    transpose_h_kernel<<<dim3(Ee/32, FF/32), 256>>>(w_proj, p_wpj, FF, Ee);
    gemm_h<0, true><<<g1, 256, GT_SMEM>>>(p_fc, p_wpj,
        b_proj, nullptr, nullptr, p_x2, out, nullptr, nullptr, nullptr, M_ROWS, Ee, FF);
}

// round 12
// speedup vs baseline: 1.0703x; 1.0703x over previous
#include <cuda_runtime.h>
#include <cuda_fp16.h>
#include <math.h>
#include <stdint.h>

#define Bb 4
#define Tt 4096
#define Ee 1024
#define Hh 16
#define Dd 64
#define M_ROWS (Bb*Tt)          // 16384
#define FF (4*Ee)               // 4096
#define PIO2 1.5707963267948966f

// ===================== PTX helpers (baseline ISA only) =====================
__device__ __forceinline__ uint32_t smem_to_u32(const void* p) {
    uint32_t a;
    asm("{ .reg .u64 t; cvta.to.shared.u64 t, %1; cvt.u32.u64 %0, t; }" : "=r"(a) : "l"(p));
    return a;
}
#define CP_ASYNC16(saddr, gptr) \
    asm volatile("cp.async.cg.shared.global [%0], [%1], 16;" :: "r"(saddr), "l"(gptr))
#define CP_COMMIT() asm volatile("cp.async.commit_group;" ::: "memory")
#define CP_WAIT1()  asm volatile("cp.async.wait_group 1;" ::: "memory")

#define LDSM_X4(r0,r1,r2,r3, addr) \
    asm volatile("ldmatrix.sync.aligned.m8n8.x4.shared.b16 {%0,%1,%2,%3}, [%4];" \
        : "=r"(r0),"=r"(r1),"=r"(r2),"=r"(r3) : "r"(addr))

#define MMA_F16(d, a, b) \
    asm volatile("mma.sync.aligned.m16n8k16.row.col.f32.f16.f16.f32 " \
        "{%0,%1,%2,%3}, {%4,%5,%6,%7}, {%8,%9}, {%0,%1,%2,%3};" \
        : "+f"((d)[0]),"+f"((d)[1]),"+f"((d)[2]),"+f"((d)[3]) \
        : "r"((a)[0]),"r"((a)[1]),"r"((a)[2]),"r"((a)[3]), "r"((b)[0]),"r"((b)[1]))

__device__ __forceinline__ uint32_t pack_h2(float a, float b) {
    __half2 h = __floats2half2_rn(a, b);
    return *(uint32_t*)&h;
}

// ===================== scratch (device globals) =====================
__device__ __half g_h   [M_ROWS*Ee];           // LN out (fp16)
__device__ __half g_attn[M_ROWS*Ee];           // attn out (fp16)
__device__ __half g_fc  [(size_t)M_ROWS*FF];   // gelu out (fp16)
__device__ __half g_q [M_ROWS*Ee];
__device__ __half g_k [M_ROWS*Ee];
__device__ __half g_v [M_ROWS*Ee];
__device__ float g_x2[M_ROWS*Ee];
__device__ float g_kv  [Bb*Hh*128*Dd];
__device__ float g_ksum[Bb*Hh*128];
// transposed fp16 weights: [N, K]
__device__ __half g_wqkv[3*Ee*Ee];             // q|k|v stacked in N
__device__ __half g_wo  [Ee*Ee];
__device__ __half g_wfc [(size_t)FF*Ee];
__device__ __half g_wpj [(size_t)Ee*FF];

// ===================== transpose + fp16: W[K,N] -> T[N,K] ============
__global__ void transpose_h_kernel(const float* __restrict__ W,
                                   __half* __restrict__ T, int K, int N) {
    __shared__ float ts[32][33];
    int n0 = blockIdx.x * 32, k0 = blockIdx.y * 32;
    int tx = threadIdx.x & 31, ty = threadIdx.x >> 5;
#pragma unroll
    for (int i = 0; i < 32; i += 8)
        ts[ty + i][tx] = W[(size_t)(k0 + ty + i) * N + n0 + tx];
    __syncthreads();
#pragma unroll
    for (int i = 0; i < 32; i += 8)
        T[(size_t)(n0 + ty + i) * K + k0 + tx] = __float2half_rn(ts[tx][ty + i]);
}

// all three QKV weights in one launch (blockIdx.z selects)
__global__ void transpose_qkv_kernel(const float* __restrict__ wq,
                                     const float* __restrict__ wk,
                                     const float* __restrict__ wv,
                                     __half* __restrict__ T) {
    __shared__ float ts[32][33];
    const float* W = blockIdx.z == 0 ? wq : (blockIdx.z == 1 ? wk : wv);
    __half* Tz = T + (size_t)blockIdx.z * Ee * Ee;
    int n0 = blockIdx.x * 32, k0 = blockIdx.y * 32;
    int tx = threadIdx.x & 31, ty = threadIdx.x >> 5;
#pragma unroll
    for (int i = 0; i < 32; i += 8)
        ts[ty + i][tx] = W[(size_t)(k0 + ty + i) * Ee + n0 + tx];
    __syncthreads();
#pragma unroll
    for (int i = 0; i < 32; i += 8)
        Tz[(size_t)(n0 + ty + i) * Ee + k0 + tx] = __float2half_rn(ts[tx][ty + i]);
}

// ===================== LayerNorm -> fp16 =====================
__global__ void ln_kernel(const float* __restrict__ X, const float* __restrict__ w,
                          const float* __restrict__ b, __half* __restrict__ Y) {
    int row = blockIdx.x;
    int tid = threadIdx.x;                 // 256 threads
    const float4* x4 = (const float4*)(X + (size_t)row * Ee);
    float4 v = x4[tid];
    __shared__ float red[8];

    float s = v.x + v.y + v.z + v.w;
    for (int o = 16; o > 0; o >>= 1) s += __shfl_down_sync(0xffffffffu, s, o);
    if ((tid & 31) == 0) red[tid >> 5] = s;
    __syncthreads();
    if (tid < 8) {
        float t = red[tid];
        for (int o = 4; o > 0; o >>= 1) t += __shfl_down_sync(0xffu, t, o);
        if (tid == 0) red[0] = t;
    }
    __syncthreads();
    float mu = red[0] * (1.0f / Ee);
    __syncthreads();

    float dx = v.x - mu, dy = v.y - mu, dz = v.z - mu, dw = v.w - mu;
    float ss = dx*dx + dy*dy + dz*dz + dw*dw;
    for (int o = 16; o > 0; o >>= 1) ss += __shfl_down_sync(0xffffffffu, ss, o);
    if ((tid & 31) == 0) red[tid >> 5] = ss;
    __syncthreads();
    if (tid < 8) {
        float t = red[tid];
        for (int o = 4; o > 0; o >>= 1) t += __shfl_down_sync(0xffu, t, o);
        if (tid == 0) red[0] = t;
    }
    __syncthreads();
    float rstd = rsqrtf(red[0] * (1.0f / Ee) + 1e-5f);

    float4 wv = ((const float4*)w)[tid];
    float4 bv = ((const float4*)b)[tid];
    uint32_t h0 = pack_h2(dx * rstd * wv.x + bv.x, dy * rstd * wv.y + bv.y);
    uint32_t h1 = pack_h2(dz * rstd * wv.z + bv.z, dw * rstd * wv.w + bv.w);
    *(uint2*)&Y[(size_t)row * Ee + tid * 4] = make_uint2(h0, h1);
}

// ===================== fp16 mma.sync GEMM (R10 single-buffer mainloop) =====
// C[m,n] = act( A[m,:] @ Bt[n,:]^T + bias[n] ) (+ res)
// Tile 128x128, K-chunk 64, 3-stage cp.async, 8 warps, 2 CTAs/SM.
// ACT: 0 none (fp32 out+res), 2 gelu (fp16 out), 3 fused-QKV (fp16 out x3, relu sec<2).
#define STAGE_BYTES 32768
#define GT_SMEM (3*STAGE_BYTES)  // 96KB -> 2 CTAs/SM

__device__ __forceinline__ void load_stage(
    uint32_t sbase, int slot, int tid, int m0, int n0, int k0, int K,
    const __half* A, const __half* B)
{
    uint32_t sb = sbase + slot * STAGE_BYTES;
#pragma unroll
    for (int i = 0; i < 4; i++) {
        int u = tid + i * 256;        // 0..1023: 128 rows x 8 16B-chunks
        int r = u >> 3, c = u & 7;
        uint32_t soff = (uint32_t)(r * 128) + (uint32_t)(((c ^ (r & 7)) << 4));
        CP_ASYNC16(sb + soff, A + (size_t)(m0 + r) * K + k0 + c * 8);
    }
#pragma unroll
    for (int i = 0; i < 4; i++) {
        int u = tid + i * 256;
        int r = u >> 3, c = u & 7;
        uint32_t soff = (uint32_t)(r * 128) + (uint32_t)(((c ^ (r & 7)) << 4));
        CP_ASYNC16(sb + 16384 + soff, B + (size_t)(n0 + r) * K + k0 + c * 8);
    }
}

template<int ACT, bool RES>
__global__ __launch_bounds__(256, 2) void gemm_h(
    const __half* __restrict__ A, const __half* __restrict__ Bt,
    const float* __restrict__ bias, const float* __restrict__ bias2,
    const float* __restrict__ bias3, const float* __restrict__ res,
    float* __restrict__ Cf,
    __half* __restrict__ Ch, __half* __restrict__ Ch2, __half* __restrict__ Ch3,
    int M, int N, int K)
{
    extern __shared__ char smem[];
    uint32_t sbase = smem_to_u32(smem);
    int tid = threadIdx.x;
    int wid = tid >> 5, l = tid & 31;
    int warpM = wid >> 2, warpN = wid & 3;     // 2 x 4 warps, warp tile 64x32
    int m0 = blockIdx.y * 128, n0 = blockIdx.x * 128;

    int g = l & 7, grp = l >> 3;
    uint32_t constA = (uint32_t)((warpM * 64 + (grp & 1) * 8 + g) * 128);
    int khA = grp >> 1;
    uint32_t constB = (uint32_t)((warpN * 32 + (grp >> 1) * 8 + g) * 128);
    int khB = grp & 1;

    float acc[4][4][4];
#pragma unroll
    for (int mi = 0; mi < 4; mi++)
#pragma unroll
        for (int ni = 0; ni < 4; ni++)
#pragma unroll
            for (int j = 0; j < 4; j++) acc[mi][ni][j] = 0.0f;

    const int NC = K >> 6;                 // K-chunk 64
    load_stage(sbase, 0, tid, m0, n0, 0, K, A, Bt);
    CP_COMMIT();
    load_stage(sbase, 1, tid, m0, n0, 64, K, A, Bt);
    CP_COMMIT();

    int slot = 0, nslot = 2;
    for (int c = 0; c < NC; c++) {
        CP_WAIT1();
        __syncthreads();     // chunk c visible; all warps done with old slot data
        if (c + 2 < NC)
            load_stage(sbase, nslot, tid, m0, n0, (c + 2) * 64, K, A, Bt);
        CP_COMMIT();
        uint32_t sA = sbase + slot * STAGE_BYTES;
        uint32_t sB = sA + 16384;
#pragma unroll
        for (int ks = 0; ks < 4; ks++) {
            uint32_t Af[4][4], Bf[4][2];
            uint32_t segA = (uint32_t)(((ks * 2 + khA) ^ g) << 4);
            uint32_t segB = (uint32_t)(((ks * 2 + khB) ^ g) << 4);
#pragma unroll
            for (int mi = 0; mi < 4; mi++) {
                uint32_t ad = sA + constA + mi * 2048 + segA;
                LDSM_X4(Af[mi][0], Af[mi][1], Af[mi][2], Af[mi][3], ad);
            }
#pragma unroll
            for (int np = 0; np < 2; np++) {
                uint32_t bd = sB + constB + np * 2048 + segB;
                uint32_t t0, t1, t2, t3;
                LDSM_X4(t0, t1, t2, t3, bd);
                Bf[np*2][0] = t0; Bf[np*2][1] = t1;
                Bf[np*2+1][0] = t2; Bf[np*2+1][1] = t3;
            }
#pragma unroll
            for (int mi = 0; mi < 4; mi++)
#pragma unroll
                for (int ni = 0; ni < 4; ni++)
                    MMA_F16(acc[mi][ni], Af[mi], Bf[ni]);
        }
        slot = slot == 2 ? 0 : slot + 1;
        nslot = nslot == 2 ? 0 : nslot + 1;
    }

    // ---------------- epilogue ----------------
    int sec = n0 >> 10;                       // uniform per CTA (ACT3)
    const float* bsel = (ACT == 3) ? (sec == 0 ? bias : (sec == 1 ? bias2 : bias3)) : bias;
    __half* hsel = (ACT == 3) ? (sec == 0 ? Ch : (sec == 1 ? Ch2 : Ch3)) : Ch;
    int nsub = (ACT == 3) ? (sec << 10) : 0;
    int rowstride = (ACT == 3) ? Ee : N;
#pragma unroll
    for (int mi = 0; mi < 4; mi++) {
#pragma unroll
        for (int half_ = 0; half_ < 2; half_++) {
            int m = m0 + warpM * 64 + mi * 16 + (l >> 2) + half_ * 8;
#pragma unroll
            for (int ni = 0; ni < 4; ni++) {
                int n = n0 + warpN * 32 + ni * 8 + (l & 3) * 2;
                float v0 = acc[mi][ni][half_ * 2 + 0];
                float v1 = acc[mi][ni][half_ * 2 + 1];
                float2 bz = __ldg((const float2*)&bsel[n - nsub]);
                v0 += bz.x; v1 += bz.y;
                if (ACT == 3 && sec < 2) {
                    v0 = fmaxf(v0, 0.0f); v1 = fmaxf(v1, 0.0f);
                } else if (ACT == 2) {
                    v0 = 0.5f * v0 * (1.0f + erff(v0 * 0.70710678118654752f));
                    v1 = 0.5f * v1 * (1.0f + erff(v1 * 0.70710678118654752f));
                }
                size_t off = (size_t)m * rowstride + (n - nsub);
                if (RES) {
                    float2 rv = *(const float2*)&res[off];
                    v0 += rv.x; v1 += rv.y;
                }
                if (ACT == 0) {
                    *(float2*)&Cf[off] = make_float2(v0, v1);
                } else {
                    *(uint32_t*)&hsel[off] = pack_h2(v0, v1);
                }
            }
        }
    }
}

// ===================== zero (kv + ksum in one launch) =====================
__global__ void zero2_kernel(float* p1, int n1, float* p2, int n2) {
    int i = blockIdx.x * blockDim.x + threadIdx.x;
    if (i < n1) p1[i] = 0.0f;
    if (i < n2) p2[i] = 0.0f;
}

// ===================== kv reduction (fp16 inputs) =====================
#define TSPLIT 8
__global__ __launch_bounds__(256) void kv_kernel(
    const __half* __restrict__ Kp, const __half* __restrict__ Vp,
    float* __restrict__ kv, float* __restrict__ ksum)
{
    int bh = blockIdx.x;
    int b = bh >> 4, h = bh & 15;
    int tid = threadIdx.x;
    __shared__ float ks_sh[32][64];
    __shared__ float vs_sh[32][64];
    __shared__ float s_sh[32], c_sh[32];

    int dd = tid & 63;
    int eb = tid >> 6;
    int e0 = eb * 16;
    float acc_s[16], acc_c[16];
#pragma unroll
    for (int i = 0; i < 16; i++) { acc_s[i] = 0.0f; acc_c[i] = 0.0f; }
    float ksum_s = 0.0f, ksum_c = 0.0f;

    int rr = tid >> 3, c8 = (tid & 7) * 8;       // 256 threads -> 32 rows x 8 cols-of-8
    int tbase = blockIdx.y * (Tt / TSPLIT);
    for (int tt = 0; tt < Tt / TSPLIT; tt += 32) {
        int t0 = tbase + tt;
        {
            size_t off = (size_t)(b * Tt + t0 + rr) * Ee + h * 64 + c8;
            uint4 kk = *(const uint4*)&Kp[off];
            uint4 vv = *(const uint4*)&Vp[off];
            const __half2* kh = (const __half2*)&kk;
            const __half2* vh = (const __half2*)&vv;
#pragma unroll
            for (int j = 0; j < 4; j++) {
                float2 kf = __half22float2(kh[j]);
                float2 vf = __half22float2(vh[j]);
                ks_sh[rr][c8 + j*2 + 0] = kf.x;
                ks_sh[rr][c8 + j*2 + 1] = kf.y;
                vs_sh[rr][c8 + j*2 + 0] = vf.x;
                vs_sh[rr][c8 + j*2 + 1] = vf.y;
            }
        }
        if (tid < 32) {
            float idx = PIO2 * (float)(t0 + tid + 1) * (1.0f / Tt);
            s_sh[tid] = sinf(idx);
            c_sh[tid] = cosf(idx);
        }
        __syncthreads();
#pragma unroll 4
        for (int r = 0; r < 32; r++) {
            float kd = ks_sh[r][dd];
            float as = kd * s_sh[r];
            float ac = kd * c_sh[r];
            if (eb == 0) { ksum_s += as; ksum_c += ac; }
#pragma unroll
            for (int i = 0; i < 16; i++) {
                float ve = vs_sh[r][e0 + i];
                acc_s[i] = fmaf(as, ve, acc_s[i]);
                acc_c[i] = fmaf(ac, ve, acc_c[i]);
            }
        }
        __syncthreads();
    }
    float* kvb = kv + (size_t)bh * 128 * Dd;
#pragma unroll
    for (int i = 0; i < 16; i++) {
        atomicAdd(&kvb[dd * Dd + e0 + i], acc_s[i]);
        atomicAdd(&kvb[(64 + dd) * Dd + e0 + i], acc_c[i]);
    }
    if (eb == 0) {
        atomicAdd(&ksum[bh * 128 + dd], ksum_s);
        atomicAdd(&ksum[bh * 128 + 64 + dd], ksum_c);
    }
}

// ===================== attention (fp16 q in, fp16 out) =================
__global__ __launch_bounds__(256) void attn_kernel(
    const __half* __restrict__ Qp, const float* __restrict__ kv,
    const float* __restrict__ ksum, __half* __restrict__ Op)
{
    int bh = blockIdx.y;
    int b = bh >> 4, h = bh & 15;
    int t0 = blockIdx.x * 32;
    int tid = threadIdx.x;

    __shared__ float kv_sh[128][64];
    __shared__ float q_sh[32][65];
    __shared__ float ksum_sh[128];
    __shared__ float den_sh[32], s_sh[32], c_sh[32];

#pragma unroll
    for (int ld = 0; ld < 8; ld++) {
        int id = tid + ld * 256;
        int r = id >> 4, c4 = (id & 15) * 4;
        *(float4*)&kv_sh[r][c4] = *(const float4*)&kv[((size_t)bh * 128 + r) * Dd + c4];
    }
    {
        int rr = tid >> 3, c8 = (tid & 7) * 8;
        uint4 qq = *(const uint4*)&Qp[(size_t)(b * Tt + t0 + rr) * Ee + h * 64 + c8];
        const __half2* qh = (const __half2*)&qq;
#pragma unroll
        for (int j = 0; j < 4; j++) {
            float2 qf = __half22float2(qh[j]);
            q_sh[rr][c8 + j*2 + 0] = qf.x;
            q_sh[rr][c8 + j*2 + 1] = qf.y;
        }
    }
    if (tid < 128) ksum_sh[tid] = ksum[bh * 128 + tid];
    if (tid < 32) {
        float idx = PIO2 * (float)(t0 + tid + 1) * (1.0f / Tt);
        s_sh[tid] = sinf(idx);
        c_sh[tid] = cosf(idx);
    }
    __syncthreads();

    if (tid < 32) {
        float ds = 0.0f, dc = 0.0f;
#pragma unroll 8
        for (int d = 0; d < 64; d++) {
            float qd = q_sh[tid][d];
            ds = fmaf(qd, ksum_sh[d], ds);
            dc = fmaf(qd, ksum_sh[64 + d], dc);
        }
        den_sh[tid] = s_sh[tid] * ds + c_sh[tid] * dc;
    }
    __syncthreads();

    int tl = tid & 31;
    int eb = tid >> 5;
    int e0 = eb * 8;
    float outs[8], outc[8];
#pragma unroll
    for (int j = 0; j < 8; j++) { outs[j] = 0.0f; outc[j] = 0.0f; }

#pragma unroll 4
    for (int d = 0; d < 64; d++) {
        float qd = q_sh[tl][d];
        float4 k0 = *(const float4*)&kv_sh[d][e0];
        float4 k1 = *(const float4*)&kv_sh[d][e0 + 4];
        float4 m0 = *(const float4*)&kv_sh[64 + d][e0];
        float4 m1 = *(const float4*)&kv_sh[64 + d][e0 + 4];
        outs[0]=fmaf(qd,k0.x,outs[0]); outs[1]=fmaf(qd,k0.y,outs[1]);
        outs[2]=fmaf(qd,k0.z,outs[2]); outs[3]=fmaf(qd,k0.w,outs[3]);
        outs[4]=fmaf(qd,k1.x,outs[4]); outs[5]=fmaf(qd,k1.y,outs[5]);
        outs[6]=fmaf(qd,k1.z,outs[6]); outs[7]=fmaf(qd,k1.w,outs[7]);
        outc[0]=fmaf(qd,m0.x,outc[0]); outc[1]=fmaf(qd,m0.y,outc[1]);
        outc[2]=fmaf(qd,m0.z,outc[2]); outc[3]=fmaf(qd,m0.w,outc[3]);
        outc[4]=fmaf(qd,m1.x,outc[4]); outc[5]=fmaf(qd,m1.y,outc[5]);
        outc[6]=fmaf(qd,m1.z,outc[6]); outc[7]=fmaf(qd,m1.w,outc[7]);
    }
    float z = 1.0f / fmaxf(den_sh[tl], 1e-6f);
    float s = s_sh[tl] * z, c = c_sh[tl] * z;
    uint32_t hp[4];
#pragma unroll
    for (int j = 0; j < 8; j += 2)
        hp[j >> 1] = pack_h2(s * outs[j] + c * outc[j], s * outs[j+1] + c * outc[j+1]);
    size_t off = (size_t)(b * Tt + t0 + tl) * Ee + h * 64 + e0;
    *(uint4*)&Op[off] = make_uint4(hp[0], hp[1], hp[2], hp[3]);
}

// ===================== launch =====================
extern "C" void kernel_launch(void* const* d_in, const int* in_sizes, int n_in,
                              void* d_out, int out_size) {
    const float* x      = (const float*)d_in[0];
    const float* ln1_w  = (const float*)d_in[1];
    const float* ln1_b  = (const float*)d_in[2];
    const float* wq     = (const float*)d_in[3];
    const float* bq     = (const float*)d_in[4];
    const float* wk     = (const float*)d_in[5];
    const float* bk     = (const float*)d_in[6];
    const float* wv     = (const float*)d_in[7];
    const float* bv     = (const float*)d_in[8];
    const float* wo     = (const float*)d_in[9];
    const float* bo     = (const float*)d_in[10];
    const float* ln2_w  = (const float*)d_in[11];
    const float* ln2_b  = (const float*)d_in[12];
    const float* w_fc   = (const float*)d_in[13];
    const float* b_fc   = (const float*)d_in[14];
    const float* w_proj = (const float*)d_in[15];
    const float* b_proj = (const float*)d_in[16];
    float* out = (float*)d_out;

    __half *p_h, *p_attn, *p_fc, *p_q, *p_k, *p_v;
    __half *p_wqkv, *p_wo, *p_wfc, *p_wpj;
    float *p_x2, *p_kv, *p_ksum;
    cudaGetSymbolAddress((void**)&p_h,    g_h);
    cudaGetSymbolAddress((void**)&p_attn, g_attn);
    cudaGetSymbolAddress((void**)&p_fc,   g_fc);
    cudaGetSymbolAddress((void**)&p_q,    g_q);
    cudaGetSymbolAddress((void**)&p_k,    g_k);
    cudaGetSymbolAddress((void**)&p_v,    g_v);
    cudaGetSymbolAddress((void**)&p_x2,   g_x2);
    cudaGetSymbolAddress((void**)&p_kv,   g_kv);
    cudaGetSymbolAddress((void**)&p_ksum, g_ksum);
    cudaGetSymbolAddress((void**)&p_wqkv, g_wqkv);
    cudaGetSymbolAddress((void**)&p_wo,   g_wo);
    cudaGetSymbolAddress((void**)&p_wfc,  g_wfc);
    cudaGetSymbolAddress((void**)&p_wpj,  g_wpj);

    cudaFuncSetAttribute(gemm_h<3, false>, cudaFuncAttributeMaxDynamicSharedMemorySize, GT_SMEM);
    cudaFuncSetAttribute(gemm_h<0, true>,  cudaFuncAttributeMaxDynamicSharedMemorySize, GT_SMEM);
    cudaFuncSetAttribute(gemm_h<2, false>, cudaFuncAttributeMaxDynamicSharedMemorySize, GT_SMEM);

    // launch 0: h = LN1(x)
    ln_kernel<<<M_ROWS, 256>>>(x, ln1_w, ln1_b, p_h);
    // launch 1: QKV weight transpose (all 3 in one launch)
    transpose_qkv_kernel<<<dim3(Ee/32, Ee/32, 3), 256>>>(wq, wk, wv, p_wqkv);
    // launch 2: wo transpose
    transpose_h_kernel<<<dim3(Ee/32, Ee/32), 256>>>(wo, p_wo, Ee, Ee);
    // launch 3 (ncu capture target): fused QKV GEMM, N=3072, fp16 outputs
    dim3 gqkv(3*Ee / 128, M_ROWS / 128);
    gemm_h<3, false><<<gqkv, 256, GT_SMEM>>>(p_h, p_wqkv,
        bq, bk, bv, nullptr, nullptr, p_q, p_k, p_v, M_ROWS, 3*Ee, Ee);

    // kv / ksum reduction
    zero2_kernel<<<(Bb*Hh*128*Dd + 255) / 256, 256>>>(p_kv, Bb*Hh*128*Dd, p_ksum, Bb*Hh*128);
    kv_kernel<<<dim3(Bb * Hh, TSPLIT), 256>>>(p_k, p_v, p_kv, p_ksum);

    // attention output (fp16)
    attn_kernel<<<dim3(Tt / 32, Bb * Hh), 256>>>(p_q, p_kv, p_ksum, p_attn);

    // x2 = x + attn @ wo + bo
    dim3 g1(Ee / 128, M_ROWS / 128);
    gemm_h<0, true><<<g1, 256, GT_SMEM>>>(p_attn, p_wo,
        bo, nullptr, nullptr, x, p_x2, nullptr, nullptr, nullptr, M_ROWS, Ee, Ee);

    // h = LN2(x2)
    ln_kernel<<<M_ROWS, 256>>>(p_x2, ln2_w, ln2_b, p_h);

    // fc = gelu(h @ w_fc + b_fc)  (fp16 out)
    transpose_h_kernel<<<dim3(FF/32, Ee/32), 256>>>(w_fc, p_wfc, Ee, FF);
    dim3 g2(FF / 128, M_ROWS / 128);
    gemm_h<2, false><<<g2, 256, GT_SMEM>>>(p_h, p_wfc,
        b_fc, nullptr, nullptr, nullptr, nullptr, p_fc, nullptr, nullptr, M_ROWS, FF, Ee);

    // out = x2 + fc @ w_proj + b_proj
    transpose_h_kernel<<<dim3(Ee/32, FF/32), 256>>>(w_proj, p_wpj, FF, Ee);
    gemm_h<0, true><<<g1, 256, GT_SMEM>>>(p_fc, p_wpj,
        b_proj, nullptr, nullptr, p_x2, out, nullptr, nullptr, nullptr, M_ROWS, Ee, FF);
}

// round 15
// speedup vs baseline: 1.0840x; 1.0128x over previous
#include <cuda_runtime.h>
#include <cuda_fp16.h>
#include <math.h>
#include <stdint.h>

#define Bb 4
#define Tt 4096
#define Ee 1024
#define Hh 16
#define Dd 64
#define M_ROWS (Bb*Tt)          // 16384
#define FF (4*Ee)               // 4096
#define PIO2 1.5707963267948966f

// ===================== PTX helpers (baseline ISA only) =====================
__device__ __forceinline__ uint32_t smem_to_u32(const void* p) {
    uint32_t a;
    asm("{ .reg .u64 t; cvta.to.shared.u64 t, %1; cvt.u32.u64 %0, t; }" : "=r"(a) : "l"(p));
    return a;
}
#define CP_ASYNC16(saddr, gptr) \
    asm volatile("cp.async.cg.shared.global [%0], [%1], 16;" :: "r"(saddr), "l"(gptr))
#define CP_COMMIT() asm volatile("cp.async.commit_group;" ::: "memory")
#define CP_WAIT1()  asm volatile("cp.async.wait_group 1;" ::: "memory")

#define LDSM_X4(r0,r1,r2,r3, addr) \
    asm volatile("ldmatrix.sync.aligned.m8n8.x4.shared.b16 {%0,%1,%2,%3}, [%4];" \
        : "=r"(r0),"=r"(r1),"=r"(r2),"=r"(r3) : "r"(addr))

#define MMA_F16(d, a, b) \
    asm volatile("mma.sync.aligned.m16n8k16.row.col.f32.f16.f16.f32 " \
        "{%0,%1,%2,%3}, {%4,%5,%6,%7}, {%8,%9}, {%0,%1,%2,%3};" \
        : "+f"((d)[0]),"+f"((d)[1]),"+f"((d)[2]),"+f"((d)[3]) \
        : "r"((a)[0]),"r"((a)[1]),"r"((a)[2]),"r"((a)[3]), "r"((b)[0]),"r"((b)[1]))

__device__ __forceinline__ uint32_t pack_h2(float a, float b) {
    __half2 h = __floats2half2_rn(a, b);
    return *(uint32_t*)&h;
}

// ===================== scratch (device globals) =====================
__device__ __half g_h   [M_ROWS*Ee];           // LN out (fp16)
__device__ __half g_attn[M_ROWS*Ee];           // attn out (fp16)
__device__ __half g_fc  [(size_t)M_ROWS*FF];   // gelu out (fp16)
__device__ __half g_q [M_ROWS*Ee];
__device__ __half g_k [M_ROWS*Ee];
__device__ __half g_v [M_ROWS*Ee];
__device__ float g_x2[M_ROWS*Ee];
__device__ float g_kv  [Bb*Hh*128*Dd];
__device__ float g_ksum[Bb*Hh*128];
// transposed fp16 weights: [N, K]
__device__ __half g_wqkv[3*Ee*Ee];             // q|k|v stacked in N
__device__ __half g_wo  [Ee*Ee];
__device__ __half g_wfc [(size_t)FF*Ee];
__device__ __half g_wpj [(size_t)Ee*FF];

// ===================== transpose + fp16: W[K,N] -> T[N,K] ============
__global__ void transpose_h_kernel(const float* __restrict__ W,
                                   __half* __restrict__ T, int K, int N) {
    __shared__ float ts[32][33];
    int n0 = blockIdx.x * 32, k0 = blockIdx.y * 32;
    int tx = threadIdx.x & 31, ty = threadIdx.x >> 5;
#pragma unroll
    for (int i = 0; i < 32; i += 8)
        ts[ty + i][tx] = W[(size_t)(k0 + ty + i) * N + n0 + tx];
    __syncthreads();
#pragma unroll
    for (int i = 0; i < 32; i += 8)
        T[(size_t)(n0 + ty + i) * K + k0 + tx] = __float2half_rn(ts[tx][ty + i]);
}

// all three QKV weights in one launch (blockIdx.z selects)
__global__ void transpose_qkv_kernel(const float* __restrict__ wq,
                                     const float* __restrict__ wk,
                                     const float* __restrict__ wv,
                                     __half* __restrict__ T) {
    __shared__ float ts[32][33];
    const float* W = blockIdx.z == 0 ? wq : (blockIdx.z == 1 ? wk : wv);
    __half* Tz = T + (size_t)blockIdx.z * Ee * Ee;
    int n0 = blockIdx.x * 32, k0 = blockIdx.y * 32;
    int tx = threadIdx.x & 31, ty = threadIdx.x >> 5;
#pragma unroll
    for (int i = 0; i < 32; i += 8)
        ts[ty + i][tx] = W[(size_t)(k0 + ty + i) * Ee + n0 + tx];
    __syncthreads();
#pragma unroll
    for (int i = 0; i < 32; i += 8)
        Tz[(size_t)(n0 + ty + i) * Ee + k0 + tx] = __float2half_rn(ts[tx][ty + i]);
}

// ===================== LayerNorm: one warp per row, no block syncs =========
__global__ __launch_bounds__(256) void ln_kernel(
    const float* __restrict__ X, const float* __restrict__ w,
    const float* __restrict__ b, __half* __restrict__ Y) {
    int lane = threadIdx.x & 31;
    int row = blockIdx.x * 8 + (threadIdx.x >> 5);
    const float4* x4 = (const float4*)(X + (size_t)row * Ee);

    float4 v[8];
#pragma unroll
    for (int i = 0; i < 8; i++) v[i] = x4[lane + i * 32];

    float s = 0.0f;
#pragma unroll
    for (int i = 0; i < 8; i++) s += v[i].x + v[i].y + v[i].z + v[i].w;
#pragma unroll
    for (int o = 16; o > 0; o >>= 1) s += __shfl_xor_sync(0xffffffffu, s, o);
    float mu = s * (1.0f / Ee);

    float ss = 0.0f;
#pragma unroll
    for (int i = 0; i < 8; i++) {
        float dx = v[i].x - mu, dy = v[i].y - mu, dz = v[i].z - mu, dw = v[i].w - mu;
        ss += dx*dx + dy*dy + dz*dz + dw*dw;
    }
#pragma unroll
    for (int o = 16; o > 0; o >>= 1) ss += __shfl_xor_sync(0xffffffffu, ss, o);
    float rstd = rsqrtf(ss * (1.0f / Ee) + 1e-5f);

    const float4* w4 = (const float4*)w;
    const float4* b4 = (const float4*)b;
    uint2* y2 = (uint2*)(Y + (size_t)row * Ee);
#pragma unroll
    for (int i = 0; i < 8; i++) {
        float4 wv = w4[lane + i * 32];
        float4 bv = b4[lane + i * 32];
        float ox = (v[i].x - mu) * rstd * wv.x + bv.x;
        float oy = (v[i].y - mu) * rstd * wv.y + bv.y;
        float oz = (v[i].z - mu) * rstd * wv.z + bv.z;
        float ow = (v[i].w - mu) * rstd * wv.w + bv.w;
        y2[lane + i * 32] = make_uint2(pack_h2(ox, oy), pack_h2(oz, ow));
    }
}

// ===================== fp16 mma.sync GEMM (single-buffer mainloop) =========
// C[m,n] = act( A[m,:] @ Bt[n,:]^T + bias[n] ) (+ res)
// Tile 128x128, K-chunk 64, 3-stage cp.async, 8 warps, 2 CTAs/SM.
// ACT: 0 none (fp32 out+res), 2 gelu (fp16 out), 3 fused-QKV (fp16 out x3, relu sec<2).
#define STAGE_BYTES 32768
#define GT_SMEM (3*STAGE_BYTES)  // 96KB -> 2 CTAs/SM

__device__ __forceinline__ void load_stage(
    uint32_t sbase, int slot, int tid, int m0, int n0, int k0, int K,
    const __half* A, const __half* B)
{
    uint32_t sb = sbase + slot * STAGE_BYTES;
#pragma unroll
    for (int i = 0; i < 4; i++) {
        int u = tid + i * 256;        // 0..1023: 128 rows x 8 16B-chunks
        int r = u >> 3, c = u & 7;
        uint32_t soff = (uint32_t)(r * 128) + (uint32_t)(((c ^ (r & 7)) << 4));
        CP_ASYNC16(sb + soff, A + (size_t)(m0 + r) * K + k0 + c * 8);
    }
#pragma unroll
    for (int i = 0; i < 4; i++) {
        int u = tid + i * 256;
        int r = u >> 3, c = u & 7;
        uint32_t soff = (uint32_t)(r * 128) + (uint32_t)(((c ^ (r & 7)) << 4));
        CP_ASYNC16(sb + 16384 + soff, B + (size_t)(n0 + r) * K + k0 + c * 8);
    }
}

template<int ACT, bool RES>
__global__ __launch_bounds__(256, 2) void gemm_h(
    const __half* __restrict__ A, const __half* __restrict__ Bt,
    const float* __restrict__ bias, const float* __restrict__ bias2,
    const float* __restrict__ bias3, const float* __restrict__ res,
    float* __restrict__ Cf,
    __half* __restrict__ Ch, __half* __restrict__ Ch2, __half* __restrict__ Ch3,
    int M, int N, int K)
{
    extern __shared__ char smem[];
    uint32_t sbase = smem_to_u32(smem);
    int tid = threadIdx.x;
    int wid = tid >> 5, l = tid & 31;
    int warpM = wid >> 2, warpN = wid & 3;     // 2 x 4 warps, warp tile 64x32
    int m0 = blockIdx.y * 128, n0 = blockIdx.x * 128;

    int g = l & 7, grp = l >> 3;
    uint32_t constA = (uint32_t)((warpM * 64 + (grp & 1) * 8 + g) * 128);
    int khA = grp >> 1;
    uint32_t constB = (uint32_t)((warpN * 32 + (grp >> 1) * 8 + g) * 128);
    int khB = grp & 1;

    float acc[4][4][4];
#pragma unroll
    for (int mi = 0; mi < 4; mi++)
#pragma unroll
        for (int ni = 0; ni < 4; ni++)
#pragma unroll
            for (int j = 0; j < 4; j++) acc[mi][ni][j] = 0.0f;

    const int NC = K >> 6;                 // K-chunk 64
    load_stage(sbase, 0, tid, m0, n0, 0, K, A, Bt);
    CP_COMMIT();
    load_stage(sbase, 1, tid, m0, n0, 64, K, A, Bt);
    CP_COMMIT();

    int slot = 0, nslot = 2;
    for (int c = 0; c < NC; c++) {
        CP_WAIT1();
        __syncthreads();     // chunk c visible; all warps done with old slot data
        if (c + 2 < NC)
            load_stage(sbase, nslot, tid, m0, n0, (c + 2) * 64, K, A, Bt);
        CP_COMMIT();
        uint32_t sA = sbase + slot * STAGE_BYTES;
        uint32_t sB = sA + 16384;
#pragma unroll
        for (int ks = 0; ks < 4; ks++) {
            uint32_t Af[4][4], Bf[4][2];
            uint32_t segA = (uint32_t)(((ks * 2 + khA) ^ g) << 4);
            uint32_t segB = (uint32_t)(((ks * 2 + khB) ^ g) << 4);
#pragma unroll
            for (int mi = 0; mi < 4; mi++) {
                uint32_t ad = sA + constA + mi * 2048 + segA;
                LDSM_X4(Af[mi][0], Af[mi][1], Af[mi][2], Af[mi][3], ad);
            }
#pragma unroll
            for (int np = 0; np < 2; np++) {
                uint32_t bd = sB + constB + np * 2048 + segB;
                uint32_t t0, t1, t2, t3;
                LDSM_X4(t0, t1, t2, t3, bd);
                Bf[np*2][0] = t0; Bf[np*2][1] = t1;
                Bf[np*2+1][0] = t2; Bf[np*2+1][1] = t3;
            }
#pragma unroll
            for (int mi = 0; mi < 4; mi++)
#pragma unroll
                for (int ni = 0; ni < 4; ni++)
                    MMA_F16(acc[mi][ni], Af[mi], Bf[ni]);
        }
        slot = slot == 2 ? 0 : slot + 1;
        nslot = nslot == 2 ? 0 : nslot + 1;
    }

    // ---------------- epilogue ----------------
    int sec = n0 >> 10;                       // uniform per CTA (ACT3)
    const float* bsel = (ACT == 3) ? (sec == 0 ? bias : (sec == 1 ? bias2 : bias3)) : bias;
    __half* hsel = (ACT == 3) ? (sec == 0 ? Ch : (sec == 1 ? Ch2 : Ch3)) : Ch;
    int nsub = (ACT == 3) ? (sec << 10) : 0;
    int rowstride = (ACT == 3) ? Ee : N;
#pragma unroll
    for (int mi = 0; mi < 4; mi++) {
#pragma unroll
        for (int half_ = 0; half_ < 2; half_++) {
            int m = m0 + warpM * 64 + mi * 16 + (l >> 2) + half_ * 8;
#pragma unroll
            for (int ni = 0; ni < 4; ni++) {
                int n = n0 + warpN * 32 + ni * 8 + (l & 3) * 2;
                float v0 = acc[mi][ni][half_ * 2 + 0];
                float v1 = acc[mi][ni][half_ * 2 + 1];
                float2 bz = __ldg((const float2*)&bsel[n - nsub]);
                v0 += bz.x; v1 += bz.y;
                if (ACT == 3 && sec < 2) {
                    v0 = fmaxf(v0, 0.0f); v1 = fmaxf(v1, 0.0f);
                } else if (ACT == 2) {
                    v0 = 0.5f * v0 * (1.0f + erff(v0 * 0.70710678118654752f));
                    v1 = 0.5f * v1 * (1.0f + erff(v1 * 0.70710678118654752f));
                }
                size_t off = (size_t)m * rowstride + (n - nsub);
                if (RES) {
                    float2 rv = *(const float2*)&res[off];
                    v0 += rv.x; v1 += rv.y;
                }
                if (ACT == 0) {
                    *(float2*)&Cf[off] = make_float2(v0, v1);
                } else {
                    *(uint32_t*)&hsel[off] = pack_h2(v0, v1);
                }
            }
        }
    }
}

// ===================== zero (kv + ksum in one launch) =====================
__global__ void zero2_kernel(float* p1, int n1, float* p2, int n2) {
    int i = blockIdx.x * blockDim.x + threadIdx.x;
    if (i < n1) p1[i] = 0.0f;
    if (i < n2) p2[i] = 0.0f;
}

// ===================== kv reduction (fp16 inputs, vectorized smem fill) ====
#define TSPLIT 8
__global__ __launch_bounds__(256) void kv_kernel(
    const __half* __restrict__ Kp, const __half* __restrict__ Vp,
    float* __restrict__ kv, float* __restrict__ ksum)
{
    int bh = blockIdx.x;
    int b = bh >> 4, h = bh & 15;
    int tid = threadIdx.x;
    __shared__ float ks_sh[32][64];
    __shared__ float vs_sh[32][64];
    __shared__ float s_sh[32], c_sh[32];

    int dd = tid & 63;
    int eb = tid >> 6;
    int e0 = eb * 16;
    float acc_s[16], acc_c[16];
#pragma unroll
    for (int i = 0; i < 16; i++) { acc_s[i] = 0.0f; acc_c[i] = 0.0f; }
    float ksum_s = 0.0f, ksum_c = 0.0f;

    int rr = tid >> 3, c8 = (tid & 7) * 8;       // 256 threads -> 32 rows x 8 cols-of-8
    int tbase = blockIdx.y * (Tt / TSPLIT);
    for (int tt = 0; tt < Tt / TSPLIT; tt += 32) {
        int t0 = tbase + tt;
        {
            size_t off = (size_t)(b * Tt + t0 + rr) * Ee + h * 64 + c8;
            uint4 kk = *(const uint4*)&Kp[off];
            uint4 vv = *(const uint4*)&Vp[off];
            const __half2* kh = (const __half2*)&kk;
            const __half2* vh = (const __half2*)&vv;
            float2 k0 = __half22float2(kh[0]), k1 = __half22float2(kh[1]);
            float2 k2 = __half22float2(kh[2]), k3 = __half22float2(kh[3]);
            float2 v0 = __half22float2(vh[0]), v1 = __half22float2(vh[1]);
            float2 v2 = __half22float2(vh[2]), v3 = __half22float2(vh[3]);
            *(float4*)&ks_sh[rr][c8]     = make_float4(k0.x, k0.y, k1.x, k1.y);
            *(float4*)&ks_sh[rr][c8 + 4] = make_float4(k2.x, k2.y, k3.x, k3.y);
            *(float4*)&vs_sh[rr][c8]     = make_float4(v0.x, v0.y, v1.x, v1.y);
            *(float4*)&vs_sh[rr][c8 + 4] = make_float4(v2.x, v2.y, v3.x, v3.y);
        }
        if (tid < 32) {
            float idx = PIO2 * (float)(t0 + tid + 1) * (1.0f / Tt);
            s_sh[tid] = sinf(idx);
            c_sh[tid] = cosf(idx);
        }
        __syncthreads();
#pragma unroll 4
        for (int r = 0; r < 32; r++) {
            float kd = ks_sh[r][dd];
            float as = kd * s_sh[r];
            float ac = kd * c_sh[r];
            if (eb == 0) { ksum_s += as; ksum_c += ac; }
#pragma unroll
            for (int i = 0; i < 16; i++) {
                float ve = vs_sh[r][e0 + i];
                acc_s[i] = fmaf(as, ve, acc_s[i]);
                acc_c[i] = fmaf(ac, ve, acc_c[i]);
            }
        }
        __syncthreads();
    }
    float* kvb = kv + (size_t)bh * 128 * Dd;
#pragma unroll
    for (int i = 0; i < 16; i++) {
        atomicAdd(&kvb[dd * Dd + e0 + i], acc_s[i]);
        atomicAdd(&kvb[(64 + dd) * Dd + e0 + i], acc_c[i]);
    }
    if (eb == 0) {
        atomicAdd(&ksum[bh * 128 + dd], ksum_s);
        atomicAdd(&ksum[bh * 128 + 64 + dd], ksum_c);
    }
}

// ===================== attention (fp16 q in, fp16 out) =================
__global__ __launch_bounds__(256) void attn_kernel(
    const __half* __restrict__ Qp, const float* __restrict__ kv,
    const float* __restrict__ ksum, __half* __restrict__ Op)
{
    int bh = blockIdx.y;
    int b = bh >> 4, h = bh & 15;
    int t0 = blockIdx.x * 32;
    int tid = threadIdx.x;

    __shared__ float kv_sh[128][64];
    __shared__ float q_sh[32][65];
    __shared__ float ksum_sh[128];
    __shared__ float den_sh[32], s_sh[32], c_sh[32];

#pragma unroll
    for (int ld = 0; ld < 8; ld++) {
        int id = tid + ld * 256;
        int r = id >> 4, c4 = (id & 15) * 4;
        *(float4*)&kv_sh[r][c4] = *(const float4*)&kv[((size_t)bh * 128 + r) * Dd + c4];
    }
    {
        int rr = tid >> 3, c8 = (tid & 7) * 8;
        uint4 qq = *(const uint4*)&Qp[(size_t)(b * Tt + t0 + rr) * Ee + h * 64 + c8];
        const __half2* qh = (const __half2*)&qq;
#pragma unroll
        for (int j = 0; j < 4; j++) {
            float2 qf = __half22float2(qh[j]);
            q_sh[rr][c8 + j*2 + 0] = qf.x;
            q_sh[rr][c8 + j*2 + 1] = qf.y;
        }
    }
    if (tid < 128) ksum_sh[tid] = ksum[bh * 128 + tid];
    if (tid < 32) {
        float idx = PIO2 * (float)(t0 + tid + 1) * (1.0f / Tt);
        s_sh[tid] = sinf(idx);
        c_sh[tid] = cosf(idx);
    }
    __syncthreads();

    if (tid < 32) {
        float ds = 0.0f, dc = 0.0f;
#pragma unroll 8
        for (int d = 0; d < 64; d++) {
            float qd = q_sh[tid][d];
            ds = fmaf(qd, ksum_sh[d], ds);
            dc = fmaf(qd, ksum_sh[64 + d], dc);
        }
        den_sh[tid] = s_sh[tid] * ds + c_sh[tid] * dc;
    }
    __syncthreads();

    int tl = tid & 31;
    int eb = tid >> 5;
    int e0 = eb * 8;
    float outs[8], outc[8];
#pragma unroll
    for (int j = 0; j < 8; j++) { outs[j] = 0.0f; outc[j] = 0.0f; }

#pragma unroll 4
    for (int d = 0; d < 64; d++) {
        float qd = q_sh[tl][d];
        float4 k0 = *(const float4*)&kv_sh[d][e0];
        float4 k1 = *(const float4*)&kv_sh[d][e0 + 4];
        float4 m0 = *(const float4*)&kv_sh[64 + d][e0];
        float4 m1 = *(const float4*)&kv_sh[64 + d][e0 + 4];
        outs[0]=fmaf(qd,k0.x,outs[0]); outs[1]=fmaf(qd,k0.y,outs[1]);
        outs[2]=fmaf(qd,k0.z,outs[2]); outs[3]=fmaf(qd,k0.w,outs[3]);
        outs[4]=fmaf(qd,k1.x,outs[4]); outs[5]=fmaf(qd,k1.y,outs[5]);
        outs[6]=fmaf(qd,k1.z,outs[6]); outs[7]=fmaf(qd,k1.w,outs[7]);
        outc[0]=fmaf(qd,m0.x,outc[0]); outc[1]=fmaf(qd,m0.y,outc[1]);
        outc[2]=fmaf(qd,m0.z,outc[2]); outc[3]=fmaf(qd,m0.w,outc[3]);
        outc[4]=fmaf(qd,m1.x,outc[4]); outc[5]=fmaf(qd,m1.y,outc[5]);
        outc[6]=fmaf(qd,m1.z,outc[6]); outc[7]=fmaf(qd,m1.w,outc[7]);
    }
    float z = 1.0f / fmaxf(den_sh[tl], 1e-6f);
    float s = s_sh[tl] * z, c = c_sh[tl] * z;
    uint32_t hp[4];
#pragma unroll
    for (int j = 0; j < 8; j += 2)
        hp[j >> 1] = pack_h2(s * outs[j] + c * outc[j], s * outs[j+1] + c * outc[j+1]);
    size_t off = (size_t)(b * Tt + t0 + tl) * Ee + h * 64 + e0;
    *(uint4*)&Op[off] = make_uint4(hp[0], hp[1], hp[2], hp[3]);
}

// ===================== launch =====================
extern "C" void kernel_launch(void* const* d_in, const int* in_sizes, int n_in,
                              void* d_out, int out_size) {
    const float* x      = (const float*)d_in[0];
    const float* ln1_w  = (const float*)d_in[1];
    const float* ln1_b  = (const float*)d_in[2];
    const float* wq     = (const float*)d_in[3];
    const float* bq     = (const float*)d_in[4];
    const float* wk     = (const float*)d_in[5];
    const float* bk     = (const float*)d_in[6];
    const float* wv     = (const float*)d_in[7];
    const float* bv     = (const float*)d_in[8];
    const float* wo     = (const float*)d_in[9];
    const float* bo     = (const float*)d_in[10];
    const float* ln2_w  = (const float*)d_in[11];
    const float* ln2_b  = (const float*)d_in[12];
    const float* w_fc   = (const float*)d_in[13];
    const float* b_fc   = (const float*)d_in[14];
    const float* w_proj = (const float*)d_in[15];
    const float* b_proj = (const float*)d_in[16];
    float* out = (float*)d_out;

    __half *p_h, *p_attn, *p_fc, *p_q, *p_k, *p_v;
    __half *p_wqkv, *p_wo, *p_wfc, *p_wpj;
    float *p_x2, *p_kv, *p_ksum;
    cudaGetSymbolAddress((void**)&p_h,    g_h);
    cudaGetSymbolAddress((void**)&p_attn, g_attn);
    cudaGetSymbolAddress((void**)&p_fc,   g_fc);
    cudaGetSymbolAddress((void**)&p_q,    g_q);
    cudaGetSymbolAddress((void**)&p_k,    g_k);
    cudaGetSymbolAddress((void**)&p_v,    g_v);
    cudaGetSymbolAddress((void**)&p_x2,   g_x2);
    cudaGetSymbolAddress((void**)&p_kv,   g_kv);
    cudaGetSymbolAddress((void**)&p_ksum, g_ksum);
    cudaGetSymbolAddress((void**)&p_wqkv, g_wqkv);
    cudaGetSymbolAddress((void**)&p_wo,   g_wo);
    cudaGetSymbolAddress((void**)&p_wfc,  g_wfc);
    cudaGetSymbolAddress((void**)&p_wpj,  g_wpj);

    cudaFuncSetAttribute(gemm_h<3, false>, cudaFuncAttributeMaxDynamicSharedMemorySize, GT_SMEM);
    cudaFuncSetAttribute(gemm_h<0, true>,  cudaFuncAttributeMaxDynamicSharedMemorySize, GT_SMEM);
    cudaFuncSetAttribute(gemm_h<2, false>, cudaFuncAttributeMaxDynamicSharedMemorySize, GT_SMEM);

    // launch 0: h = LN1(x)   (warp-per-row)
    ln_kernel<<<M_ROWS / 8, 256>>>(x, ln1_w, ln1_b, p_h);
    // launch 1: QKV weight transpose (all 3 in one launch)
    transpose_qkv_kernel<<<dim3(Ee/32, Ee/32, 3), 256>>>(wq, wk, wv, p_wqkv);
    // launch 2: wo transpose
    transpose_h_kernel<<<dim3(Ee/32, Ee/32), 256>>>(wo, p_wo, Ee, Ee);
    // launch 3 (ncu capture target): fused QKV GEMM, N=3072, fp16 outputs
    dim3 gqkv(3*Ee / 128, M_ROWS / 128);
    gemm_h<3, false><<<gqkv, 256, GT_SMEM>>>(p_h, p_wqkv,
        bq, bk, bv, nullptr, nullptr, p_q, p_k, p_v, M_ROWS, 3*Ee, Ee);

    // kv / ksum reduction
    zero2_kernel<<<(Bb*Hh*128*Dd + 255) / 256, 256>>>(p_kv, Bb*Hh*128*Dd, p_ksum, Bb*Hh*128);
    kv_kernel<<<dim3(Bb * Hh, TSPLIT), 256>>>(p_k, p_v, p_kv, p_ksum);

    // attention output (fp16)
    attn_kernel<<<dim3(Tt / 32, Bb * Hh), 256>>>(p_q, p_kv, p_ksum, p_attn);

    // x2 = x + attn @ wo + bo
    dim3 g1(Ee / 128, M_ROWS / 128);
    gemm_h<0, true><<<g1, 256, GT_SMEM>>>(p_attn, p_wo,
        bo, nullptr, nullptr, x, p_x2, nullptr, nullptr, nullptr, M_ROWS, Ee, Ee);

    // h = LN2(x2)
    ln_kernel<<<M_ROWS / 8, 256>>>(p_x2, ln2_w, ln2_b, p_h);

    // fc = gelu(h @ w_fc + b_fc)  (fp16 out)
    transpose_h_kernel<<<dim3(FF/32, Ee/32), 256>>>(w_fc, p_wfc, Ee, FF);
    dim3 g2(FF / 128, M_ROWS / 128);
    gemm_h<2, false><<<g2, 256, GT_SMEM>>>(p_h, p_wfc,
        b_fc, nullptr, nullptr, nullptr, nullptr, p_fc, nullptr, nullptr, M_ROWS, FF, Ee);

    // out = x2 + fc @ w_proj + b_proj
    transpose_h_kernel<<<dim3(Ee/32, FF/32), 256>>>(w_proj, p_wpj, FF, Ee);
    gemm_h<0, true><<<g1, 256, GT_SMEM>>>(p_fc, p_wpj,
        b_proj, nullptr, nullptr, p_x2, out, nullptr, nullptr, nullptr, M_ROWS, Ee, FF);
}

// round 17
// speedup vs baseline: 1.1932x; 1.1007x over previous
#include <cuda_runtime.h>
#include <cuda_fp16.h>
#include <math.h>
#include <stdint.h>

#define Bb 4
#define Tt 4096
#define Ee 1024
#define Hh 16
#define Dd 64
#define M_ROWS (Bb*Tt)          // 16384
#define FF (4*Ee)               // 4096
#define PIO2 1.5707963267948966f

// ===================== PTX helpers (baseline ISA only) =====================
__device__ __forceinline__ uint32_t smem_to_u32(const void* p) {
    uint32_t a;
    asm("{ .reg .u64 t; cvta.to.shared.u64 t, %1; cvt.u32.u64 %0, t; }" : "=r"(a) : "l"(p));
    return a;
}
#define CP_ASYNC16(saddr, gptr) \
    asm volatile("cp.async.cg.shared.global [%0], [%1], 16;" :: "r"(saddr), "l"(gptr))
#define CP_COMMIT() asm volatile("cp.async.commit_group;" ::: "memory")
#define CP_WAIT1()  asm volatile("cp.async.wait_group 1;" ::: "memory")
#define CP_WAIT0()  asm volatile("cp.async.wait_group 0;" ::: "memory")

#define LDSM_X4(r0,r1,r2,r3, addr) \
    asm volatile("ldmatrix.sync.aligned.m8n8.x4.shared.b16 {%0,%1,%2,%3}, [%4];" \
        : "=r"(r0),"=r"(r1),"=r"(r2),"=r"(r3) : "r"(addr))

#define MMA_F16(d, a, b) \
    asm volatile("mma.sync.aligned.m16n8k16.row.col.f32.f16.f16.f32 " \
        "{%0,%1,%2,%3}, {%4,%5,%6,%7}, {%8,%9}, {%0,%1,%2,%3};" \
        : "+f"((d)[0]),"+f"((d)[1]),"+f"((d)[2]),"+f"((d)[3]) \
        : "r"((a)[0]),"r"((a)[1]),"r"((a)[2]),"r"((a)[3]), "r"((b)[0]),"r"((b)[1]))

__device__ __forceinline__ uint32_t pack_h2(float a, float b) {
    __half2 h = __floats2half2_rn(a, b);
    return *(uint32_t*)&h;
}

// ===================== scratch (device globals) =====================
__device__ __half g_h   [M_ROWS*Ee];           // LN out (fp16)
__device__ __half g_attn[M_ROWS*Ee];           // attn out (fp16)
__device__ __half g_fc  [(size_t)M_ROWS*FF];   // gelu out (fp16)
__device__ __half g_q [M_ROWS*Ee];
__device__ __half g_k [M_ROWS*Ee];
__device__ __half g_v [M_ROWS*Ee];
__device__ float g_x2[M_ROWS*Ee];
__device__ float g_kvt [Bb*Hh*64*128];         // kv^T fp32: [bh][e][d'] (s: d'<64, c: d'>=64)
__device__ __half g_kvh[Bb*Hh*64*128];         // fp16 copy
__device__ float g_ksum[Bb*Hh*128];
__device__ float g_z   [(size_t)Bb*Hh*Tt];     // 1/denominator per (bh, t)
// transposed fp16 weights: [N, K]
__device__ __half g_wqkv[3*Ee*Ee];             // q|k|v stacked in N
__device__ __half g_wo  [Ee*Ee];
__device__ __half g_wfc [(size_t)FF*Ee];
__device__ __half g_wpj [(size_t)Ee*FF];

// ===================== transpose + fp16: W[K,N] -> T[N,K] ============
__global__ void transpose_h_kernel(const float* __restrict__ W,
                                   __half* __restrict__ T, int K, int N) {
    __shared__ float ts[32][33];
    int n0 = blockIdx.x * 32, k0 = blockIdx.y * 32;
    int tx = threadIdx.x & 31, ty = threadIdx.x >> 5;
#pragma unroll
    for (int i = 0; i < 32; i += 8)
        ts[ty + i][tx] = W[(size_t)(k0 + ty + i) * N + n0 + tx];
    __syncthreads();
#pragma unroll
    for (int i = 0; i < 32; i += 8)
        T[(size_t)(n0 + ty + i) * K + k0 + tx] = __float2half_rn(ts[tx][ty + i]);
}

// all three QKV weights in one launch (blockIdx.z selects)
__global__ void transpose_qkv_kernel(const float* __restrict__ wq,
                                     const float* __restrict__ wk,
                                     const float* __restrict__ wv,
                                     __half* __restrict__ T) {
    __shared__ float ts[32][33];
    const float* W = blockIdx.z == 0 ? wq : (blockIdx.z == 1 ? wk : wv);
    __half* Tz = T + (size_t)blockIdx.z * Ee * Ee;
    int n0 = blockIdx.x * 32, k0 = blockIdx.y * 32;
    int tx = threadIdx.x & 31, ty = threadIdx.x >> 5;
#pragma unroll
    for (int i = 0; i < 32; i += 8)
        ts[ty + i][tx] = W[(size_t)(k0 + ty + i) * Ee + n0 + tx];
    __syncthreads();
#pragma unroll
    for (int i = 0; i < 32; i += 8)
        Tz[(size_t)(n0 + ty + i) * Ee + k0 + tx] = __float2half_rn(ts[tx][ty + i]);
}

// ===================== LayerNorm: one warp per row, no block syncs =========
__global__ __launch_bounds__(256) void ln_kernel(
    const float* __restrict__ X, const float* __restrict__ w,
    const float* __restrict__ b, __half* __restrict__ Y) {
    int lane = threadIdx.x & 31;
    int row = blockIdx.x * 8 + (threadIdx.x >> 5);
    const float4* x4 = (const float4*)(X + (size_t)row * Ee);

    float4 v[8];
#pragma unroll
    for (int i = 0; i < 8; i++) v[i] = x4[lane + i * 32];

    float s = 0.0f;
#pragma unroll
    for (int i = 0; i < 8; i++) s += v[i].x + v[i].y + v[i].z + v[i].w;
#pragma unroll
    for (int o = 16; o > 0; o >>= 1) s += __shfl_xor_sync(0xffffffffu, s, o);
    float mu = s * (1.0f / Ee);

    float ss = 0.0f;
#pragma unroll
    for (int i = 0; i < 8; i++) {
        float dx = v[i].x - mu, dy = v[i].y - mu, dz = v[i].z - mu, dw = v[i].w - mu;
        ss += dx*dx + dy*dy + dz*dz + dw*dw;
    }
#pragma unroll
    for (int o = 16; o > 0; o >>= 1) ss += __shfl_xor_sync(0xffffffffu, ss, o);
    float rstd = rsqrtf(ss * (1.0f / Ee) + 1e-5f);

    const float4* w4 = (const float4*)w;
    const float4* b4 = (const float4*)b;
    uint2* y2 = (uint2*)(Y + (size_t)row * Ee);
#pragma unroll
    for (int i = 0; i < 8; i++) {
        float4 wv = w4[lane + i * 32];
        float4 bv = b4[lane + i * 32];
        float ox = (v[i].x - mu) * rstd * wv.x + bv.x;
        float oy = (v[i].y - mu) * rstd * wv.y + bv.y;
        float oz = (v[i].z - mu) * rstd * wv.z + bv.z;
        float ow = (v[i].w - mu) * rstd * wv.w + bv.w;
        y2[lane + i * 32] = make_uint2(pack_h2(ox, oy), pack_h2(oz, ow));
    }
}

// ===================== fp16 mma.sync GEMM (single-buffer mainloop) =========
#define STAGE_BYTES 32768
#define GT_SMEM (3*STAGE_BYTES)  // 96KB -> 2 CTAs/SM

__device__ __forceinline__ void load_stage(
    uint32_t sbase, int slot, int tid, int m0, int n0, int k0, int K,
    const __half* A, const __half* B)
{
    uint32_t sb = sbase + slot * STAGE_BYTES;
#pragma unroll
    for (int i = 0; i < 4; i++) {
        int u = tid + i * 256;        // 0..1023: 128 rows x 8 16B-chunks
        int r = u >> 3, c = u & 7;
        uint32_t soff = (uint32_t)(r * 128) + (uint32_t)(((c ^ (r & 7)) << 4));
        CP_ASYNC16(sb + soff, A + (size_t)(m0 + r) * K + k0 + c * 8);
    }
#pragma unroll
    for (int i = 0; i < 4; i++) {
        int u = tid + i * 256;
        int r = u >> 3, c = u & 7;
        uint32_t soff = (uint32_t)(r * 128) + (uint32_t)(((c ^ (r & 7)) << 4));
        CP_ASYNC16(sb + 16384 + soff, B + (size_t)(n0 + r) * K + k0 + c * 8);
    }
}

template<int ACT, bool RES>
__global__ __launch_bounds__(256, 2) void gemm_h(
    const __half* __restrict__ A, const __half* __restrict__ Bt,
    const float* __restrict__ bias, const float* __restrict__ bias2,
    const float* __restrict__ bias3, const float* __restrict__ res,
    float* __restrict__ Cf,
    __half* __restrict__ Ch, __half* __restrict__ Ch2, __half* __restrict__ Ch3,
    int M, int N, int K)
{
    extern __shared__ char smem[];
    uint32_t sbase = smem_to_u32(smem);
    int tid = threadIdx.x;
    int wid = tid >> 5, l = tid & 31;
    int warpM = wid >> 2, warpN = wid & 3;     // 2 x 4 warps, warp tile 64x32
    int m0 = blockIdx.y * 128, n0 = blockIdx.x * 128;

    int g = l & 7, grp = l >> 3;
    uint32_t constA = (uint32_t)((warpM * 64 + (grp & 1) * 8 + g) * 128);
    int khA = grp >> 1;
    uint32_t constB = (uint32_t)((warpN * 32 + (grp >> 1) * 8 + g) * 128);
    int khB = grp & 1;

    float acc[4][4][4];
#pragma unroll
    for (int mi = 0; mi < 4; mi++)
#pragma unroll
        for (int ni = 0; ni < 4; ni++)
#pragma unroll
            for (int j = 0; j < 4; j++) acc[mi][ni][j] = 0.0f;

    const int NC = K >> 6;                 // K-chunk 64
    load_stage(sbase, 0, tid, m0, n0, 0, K, A, Bt);
    CP_COMMIT();
    load_stage(sbase, 1, tid, m0, n0, 64, K, A, Bt);
    CP_COMMIT();

    int slot = 0, nslot = 2;
    for (int c = 0; c < NC; c++) {
        CP_WAIT1();
        __syncthreads();
        if (c + 2 < NC)
            load_stage(sbase, nslot, tid, m0, n0, (c + 2) * 64, K, A, Bt);
        CP_COMMIT();
        uint32_t sA = sbase + slot * STAGE_BYTES;
        uint32_t sB = sA + 16384;
#pragma unroll
        for (int ks = 0; ks < 4; ks++) {
            uint32_t Af[4][4], Bf[4][2];
            uint32_t segA = (uint32_t)(((ks * 2 + khA) ^ g) << 4);
            uint32_t segB = (uint32_t)(((ks * 2 + khB) ^ g) << 4);
#pragma unroll
            for (int mi = 0; mi < 4; mi++) {
                uint32_t ad = sA + constA + mi * 2048 + segA;
                LDSM_X4(Af[mi][0], Af[mi][1], Af[mi][2], Af[mi][3], ad);
            }
#pragma unroll
            for (int np = 0; np < 2; np++) {
                uint32_t bd = sB + constB + np * 2048 + segB;
                uint32_t t0, t1, t2, t3;
                LDSM_X4(t0, t1, t2, t3, bd);
                Bf[np*2][0] = t0; Bf[np*2][1] = t1;
                Bf[np*2+1][0] = t2; Bf[np*2+1][1] = t3;
            }
#pragma unroll
            for (int mi = 0; mi < 4; mi++)
#pragma unroll
                for (int ni = 0; ni < 4; ni++)
                    MMA_F16(acc[mi][ni], Af[mi], Bf[ni]);
        }
        slot = slot == 2 ? 0 : slot + 1;
        nslot = nslot == 2 ? 0 : nslot + 1;
    }

    // ---------------- epilogue ----------------
    int sec = n0 >> 10;                       // uniform per CTA (ACT3)
    const float* bsel = (ACT == 3) ? (sec == 0 ? bias : (sec == 1 ? bias2 : bias3)) : bias;
    __half* hsel = (ACT == 3) ? (sec == 0 ? Ch : (sec == 1 ? Ch2 : Ch3)) : Ch;
    int nsub = (ACT == 3) ? (sec << 10) : 0;
    int rowstride = (ACT == 3) ? Ee : N;
#pragma unroll
    for (int mi = 0; mi < 4; mi++) {
#pragma unroll
        for (int half_ = 0; half_ < 2; half_++) {
            int m = m0 + warpM * 64 + mi * 16 + (l >> 2) + half_ * 8;
#pragma unroll
            for (int ni = 0; ni < 4; ni++) {
                int n = n0 + warpN * 32 + ni * 8 + (l & 3) * 2;
                float v0 = acc[mi][ni][half_ * 2 + 0];
                float v1 = acc[mi][ni][half_ * 2 + 1];
                float2 bz = __ldg((const float2*)&bsel[n - nsub]);
                v0 += bz.x; v1 += bz.y;
                if (ACT == 3 && sec < 2) {
                    v0 = fmaxf(v0, 0.0f); v1 = fmaxf(v1, 0.0f);
                } else if (ACT == 2) {
                    v0 = 0.5f * v0 * (1.0f + erff(v0 * 0.70710678118654752f));
                    v1 = 0.5f * v1 * (1.0f + erff(v1 * 0.70710678118654752f));
                }
                size_t off = (size_t)m * rowstride + (n - nsub);
                if (RES) {
                    float2 rv = *(const float2*)&res[off];
                    v0 += rv.x; v1 += rv.y;
                }
                if (ACT == 0) {
                    *(float2*)&Cf[off] = make_float2(v0, v1);
                } else {
                    *(uint32_t*)&hsel[off] = pack_h2(v0, v1);
                }
            }
        }
    }
}

// ===================== zero (kvt + ksum in one launch) =====================
__global__ void zero2_kernel(float* p1, int n1, float* p2, int n2) {
    int i = blockIdx.x * blockDim.x + threadIdx.x;
    if (i < n1) p1[i] = 0.0f;
    if (i < n2) p2[i] = 0.0f;
}

// ===================== kv reduction (fp16 in, kv^T fp32 out) ===============
#define TSPLIT 8
__global__ __launch_bounds__(256) void kv_kernel(
    const __half* __restrict__ Kp, const __half* __restrict__ Vp,
    float* __restrict__ kvt, float* __restrict__ ksum)
{
    int bh = blockIdx.x;
    int b = bh >> 4, h = bh & 15;
    int tid = threadIdx.x;
    __shared__ float ks_sh[32][64];
    __shared__ float vs_sh[32][64];
    __shared__ float s_sh[32], c_sh[32];

    int dd = tid & 63;
    int eb = tid >> 6;
    int e0 = eb * 16;
    float acc_s[16], acc_c[16];
#pragma unroll
    for (int i = 0; i < 16; i++) { acc_s[i] = 0.0f; acc_c[i] = 0.0f; }
    float ksum_s = 0.0f, ksum_c = 0.0f;

    int rr = tid >> 3, c8 = (tid & 7) * 8;
    int tbase = blockIdx.y * (Tt / TSPLIT);
    for (int tt = 0; tt < Tt / TSPLIT; tt += 32) {
        int t0 = tbase + tt;
        {
            size_t off = (size_t)(b * Tt + t0 + rr) * Ee + h * 64 + c8;
            uint4 kk = *(const uint4*)&Kp[off];
            uint4 vv = *(const uint4*)&Vp[off];
            const __half2* kh = (const __half2*)&kk;
            const __half2* vh = (const __half2*)&vv;
            float2 k0 = __half22float2(kh[0]), k1 = __half22float2(kh[1]);
            float2 k2 = __half22float2(kh[2]), k3 = __half22float2(kh[3]);
            float2 v0 = __half22float2(vh[0]), v1 = __half22float2(vh[1]);
            float2 v2 = __half22float2(vh[2]), v3 = __half22float2(vh[3]);
            *(float4*)&ks_sh[rr][c8]     = make_float4(k0.x, k0.y, k1.x, k1.y);
            *(float4*)&ks_sh[rr][c8 + 4] = make_float4(k2.x, k2.y, k3.x, k3.y);
            *(float4*)&vs_sh[rr][c8]     = make_float4(v0.x, v0.y, v1.x, v1.y);
            *(float4*)&vs_sh[rr][c8 + 4] = make_float4(v2.x, v2.y, v3.x, v3.y);
        }
        if (tid < 32) {
            float idx = PIO2 * (float)(t0 + tid + 1) * (1.0f / Tt);
            s_sh[tid] = sinf(idx);
            c_sh[tid] = cosf(idx);
        }
        __syncthreads();
#pragma unroll 4
        for (int r = 0; r < 32; r++) {
            float kd = ks_sh[r][dd];
            float as = kd * s_sh[r];
            float ac = kd * c_sh[r];
            if (eb == 0) { ksum_s += as; ksum_c += ac; }
#pragma unroll
            for (int i = 0; i < 16; i++) {
                float ve = vs_sh[r][e0 + i];
                acc_s[i] = fmaf(as, ve, acc_s[i]);
                acc_c[i] = fmaf(ac, ve, acc_c[i]);
            }
        }
        __syncthreads();
    }
    // transposed output: kvt[bh][e][d'] (d'<64 = s-part, d'>=64 = c-part)
    float* kvb = kvt + (size_t)bh * 64 * 128;
#pragma unroll
    for (int i = 0; i < 16; i++) {
        atomicAdd(&kvb[(e0 + i) * 128 + dd], acc_s[i]);
        atomicAdd(&kvb[(e0 + i) * 128 + 64 + dd], acc_c[i]);
    }
    if (eb == 0) {
        atomicAdd(&ksum[bh * 128 + dd], ksum_s);
        atomicAdd(&ksum[bh * 128 + 64 + dd], ksum_c);
    }
}

// ===================== kv^T fp32 -> fp16 =====================
__global__ void cvt_kvh_kernel(const float* __restrict__ kvt, __half* __restrict__ kvh) {
    int i = blockIdx.x * 256 + threadIdx.x;        // 262144 pairs
    float2 v = *(const float2*)&kvt[(size_t)i * 2];
    *(uint32_t*)&kvh[(size_t)i * 2] = pack_h2(v.x, v.y);
}

// ===================== z = 1/denominator per (bh, t) =====================
__global__ __launch_bounds__(256) void den_kernel(
    const __half* __restrict__ Qp, const float* __restrict__ ksum,
    float* __restrict__ zout)
{
    int bh = blockIdx.x, b = bh >> 4, h = bh & 15;
    __shared__ float kss[64], ksc[64];
    if (threadIdx.x < 64) kss[threadIdx.x] = ksum[bh * 128 + threadIdx.x];
    else if (threadIdx.x < 128) ksc[threadIdx.x - 64] = ksum[bh * 128 + threadIdx.x];
    __syncthreads();
    for (int t = threadIdx.x; t < Tt; t += 256) {
        const uint4* qp = (const uint4*)&Qp[(size_t)(b * Tt + t) * Ee + h * 64];
        float ds = 0.0f, dc = 0.0f;
#pragma unroll
        for (int j = 0; j < 8; j++) {
            uint4 q4 = qp[j];
            const __half2* qh = (const __half2*)&q4;
#pragma unroll
            for (int k2 = 0; k2 < 4; k2++) {
                float2 qf = __half22float2(qh[k2]);
                int d = j * 8 + k2 * 2;
                ds = fmaf(qf.x, kss[d], fmaf(qf.y, kss[d + 1], ds));
                dc = fmaf(qf.x, ksc[d], fmaf(qf.y, ksc[d + 1], dc));
            }
        }
        float idx = PIO2 * (float)(t + 1) * (1.0f / Tt);
        float den = sinf(idx) * ds + cosf(idx) * dc;
        zout[(size_t)bh * Tt + t] = 1.0f / fmaxf(den, 1e-6f);
    }
}

// ===================== attention apply via tensor cores ====================
// out[t, e] = z(t) * ( s(t) * (q @ kvs)[t,e] + c(t) * (q @ kvc)[t,e] )
// grid (Tt/128, B*H). A = q tile [128t x 64d] fp16; B = kvs/kvc [64e x 64d].
__global__ __launch_bounds__(256) void attn_mma_kernel(
    const __half* __restrict__ Qp, const __half* __restrict__ kvh,
    const float* __restrict__ zglob, __half* __restrict__ Op)
{
    __shared__ __align__(16) char smem_raw[32768];   // q 16KB | kvs 8KB | kvc 8KB
    __shared__ float s_sh[128], c_sh[128], z_sh[128];
    uint32_t sbase = smem_to_u32(smem_raw);
    int tid = threadIdx.x;
    int bh = blockIdx.y, b = bh >> 4, h = bh & 15;
    int t0 = blockIdx.x * 128;
    int wid = tid >> 5, l = tid & 31;
    int warpM = wid >> 1, warpN = wid & 1;      // 4 x 2 warps, warp tile 32x32

    // loads (same 128B-row swizzle as gemm_h)
#pragma unroll
    for (int i = 0; i < 4; i++) {
        int u = tid + i * 256;                  // q: 128 rows x 8 chunks
        int r = u >> 3, c = u & 7;
        uint32_t soff = (uint32_t)(r * 128) + (uint32_t)(((c ^ (r & 7)) << 4));
        CP_ASYNC16(sbase + soff, Qp + (size_t)(b * Tt + t0 + r) * Ee + h * 64 + c * 8);
    }
#pragma unroll
    for (int i = 0; i < 2; i++) {
        int u = tid + i * 256;                  // kv tiles: 64 rows x 8 chunks each
        int r = u >> 3, c = u & 7;
        uint32_t soff = (uint32_t)(r * 128) + (uint32_t)(((c ^ (r & 7)) << 4));
        const __half* base = kvh + (size_t)bh * 8192 + r * 128 + c * 8;
        CP_ASYNC16(sbase + 16384 + soff, base);          // s-half (cols 0..63)
        CP_ASYNC16(sbase + 24576 + soff, base + 64);     // c-half (cols 64..127)
    }
    CP_COMMIT();
    if (tid < 128) {
        float idx = PIO2 * (float)(t0 + tid + 1) * (1.0f / Tt);
        s_sh[tid] = sinf(idx);
        c_sh[tid] = cosf(idx);
        z_sh[tid] = zglob[(size_t)bh * Tt + t0 + tid];
    }
    CP_WAIT0();
    __syncthreads();

    int g = l & 7, grp = l >> 3;
    uint32_t constA = (uint32_t)((warpM * 32 + (grp & 1) * 8 + g) * 128);
    int khA = grp >> 1;
    uint32_t constB = (uint32_t)((warpN * 32 + (grp >> 1) * 8 + g) * 128);
    int khB = grp & 1;

    float accs[2][4][4], accc[2][4][4];
#pragma unroll
    for (int mi = 0; mi < 2; mi++)
#pragma unroll
        for (int ni = 0; ni < 4; ni++)
#pragma unroll
            for (int j = 0; j < 4; j++) { accs[mi][ni][j] = 0.0f; accc[mi][ni][j] = 0.0f; }

#pragma unroll
    for (int p = 0; p < 2; p++) {
        uint32_t sB = sbase + 16384 + p * 8192;
#pragma unroll
        for (int ks = 0; ks < 4; ks++) {
            uint32_t Af[2][4], Bf[4][2];
            uint32_t segA = (uint32_t)(((ks * 2 + khA) ^ g) << 4);
            uint32_t segB = (uint32_t)(((ks * 2 + khB) ^ g) << 4);
#pragma unroll
            for (int mi = 0; mi < 2; mi++) {
                uint32_t ad = sbase + constA + mi * 2048 + segA;
                LDSM_X4(Af[mi][0], Af[mi][1], Af[mi][2], Af[mi][3], ad);
            }
#pragma unroll
            for (int np = 0; np < 2; np++) {
                uint32_t bd = sB + constB + np * 2048 + segB;
                uint32_t u0, u1, u2, u3;
                LDSM_X4(u0, u1, u2, u3, bd);
                Bf[np*2][0] = u0; Bf[np*2][1] = u1;
                Bf[np*2+1][0] = u2; Bf[np*2+1][1] = u3;
            }
#pragma unroll
            for (int mi = 0; mi < 2; mi++)
#pragma unroll
                for (int ni = 0; ni < 4; ni++) {
                    if (p == 0) { MMA_F16(accs[mi][ni], Af[mi], Bf[ni]); }
                    else        { MMA_F16(accc[mi][ni], Af[mi], Bf[ni]); }
                }
        }
    }

    // epilogue: out = z * (s*accs + c*accc), fp16
#pragma unroll
    for (int mi = 0; mi < 2; mi++) {
#pragma unroll
        for (int half_ = 0; half_ < 2; half_++) {
            int mrow = warpM * 32 + mi * 16 + (l >> 2) + half_ * 8;   // 0..127
            float s = s_sh[mrow], c = c_sh[mrow], z = z_sh[mrow];
#pragma unroll
            for (int ni = 0; ni < 4; ni++) {
                int n = warpN * 32 + ni * 8 + (l & 3) * 2;
                float v0 = z * (s * accs[mi][ni][half_*2]   + c * accc[mi][ni][half_*2]);
                float v1 = z * (s * accs[mi][ni][half_*2+1] + c * accc[mi][ni][half_*2+1]);
                size_t off = (size_t)(b * Tt + t0 + mrow) * Ee + h * 64 + n;
                *(uint32_t*)&Op[off] = pack_h2(v0, v1);
            }
        }
    }
}

// ===================== launch =====================
extern "C" void kernel_launch(void* const* d_in, const int* in_sizes, int n_in,
                              void* d_out, int out_size) {
    const float* x      = (const float*)d_in[0];
    const float* ln1_w  = (const float*)d_in[1];
    const float* ln1_b  = (const float*)d_in[2];
    const float* wq     = (const float*)d_in[3];
    const float* bq     = (const float*)d_in[4];
    const float* wk     = (const float*)d_in[5];
    const float* bk     = (const float*)d_in[6];
    const float* wv     = (const float*)d_in[7];
    const float* bv     = (const float*)d_in[8];
    const float* wo     = (const float*)d_in[9];
    const float* bo     = (const float*)d_in[10];
    const float* ln2_w  = (const float*)d_in[11];
    const float* ln2_b  = (const float*)d_in[12];
    const float* w_fc   = (const float*)d_in[13];
    const float* b_fc   = (const float*)d_in[14];
    const float* w_proj = (const float*)d_in[15];
    const float* b_proj = (const float*)d_in[16];
    float* out = (float*)d_out;

    __half *p_h, *p_attn, *p_fc, *p_q, *p_k, *p_v, *p_kvh;
    __half *p_wqkv, *p_wo, *p_wfc, *p_wpj;
    float *p_x2, *p_kvt, *p_ksum, *p_z;
    cudaGetSymbolAddress((void**)&p_h,    g_h);
    cudaGetSymbolAddress((void**)&p_attn, g_attn);
    cudaGetSymbolAddress((void**)&p_fc,   g_fc);
    cudaGetSymbolAddress((void**)&p_q,    g_q);
    cudaGetSymbolAddress((void**)&p_k,    g_k);
    cudaGetSymbolAddress((void**)&p_v,    g_v);
    cudaGetSymbolAddress((void**)&p_x2,   g_x2);
    cudaGetSymbolAddress((void**)&p_kvt,  g_kvt);
    cudaGetSymbolAddress((void**)&p_kvh,  g_kvh);
    cudaGetSymbolAddress((void**)&p_ksum, g_ksum);
    cudaGetSymbolAddress((void**)&p_z,    g_z);
    cudaGetSymbolAddress((void**)&p_wqkv, g_wqkv);
    cudaGetSymbolAddress((void**)&p_wo,   g_wo);
    cudaGetSymbolAddress((void**)&p_wfc,  g_wfc);
    cudaGetSymbolAddress((void**)&p_wpj,  g_wpj);

    cudaFuncSetAttribute(gemm_h<3, false>, cudaFuncAttributeMaxDynamicSharedMemorySize, GT_SMEM);
    cudaFuncSetAttribute(gemm_h<0, true>,  cudaFuncAttributeMaxDynamicSharedMemorySize, GT_SMEM);
    cudaFuncSetAttribute(gemm_h<2, false>, cudaFuncAttributeMaxDynamicSharedMemorySize, GT_SMEM);

    // launch 0: h = LN1(x)   (warp-per-row)
    ln_kernel<<<M_ROWS / 8, 256>>>(x, ln1_w, ln1_b, p_h);
    // launch 1: QKV weight transpose (all 3 in one launch)
    transpose_qkv_kernel<<<dim3(Ee/32, Ee/32, 3), 256>>>(wq, wk, wv, p_wqkv);
    // launch 2: wo transpose
    transpose_h_kernel<<<dim3(Ee/32, Ee/32), 256>>>(wo, p_wo, Ee, Ee);
    // launch 3 (ncu capture target): fused QKV GEMM, N=3072, fp16 outputs
    dim3 gqkv(3*Ee / 128, M_ROWS / 128);
    gemm_h<3, false><<<gqkv, 256, GT_SMEM>>>(p_h, p_wqkv,
        bq, bk, bv, nullptr, nullptr, p_q, p_k, p_v, M_ROWS, 3*Ee, Ee);

    // kv / ksum reduction (kv^T layout)
    zero2_kernel<<<(Bb*Hh*64*128 + 255) / 256, 256>>>(p_kvt, Bb*Hh*64*128, p_ksum, Bb*Hh*128);
    kv_kernel<<<dim3(Bb * Hh, TSPLIT), 256>>>(p_k, p_v, p_kvt, p_ksum);
    cvt_kvh_kernel<<<(Bb*Hh*64*128/2) / 256, 256>>>(p_kvt, p_kvh);
    den_kernel<<<Bb * Hh, 256>>>(p_q, p_ksum, p_z);

    // attention apply (tensor cores)
    attn_mma_kernel<<<dim3(Tt / 128, Bb * Hh), 256>>>(p_q, p_kvh, p_z, p_attn);

    // x2 = x + attn @ wo + bo
    dim3 g1(Ee / 128, M_ROWS / 128);
    gemm_h<0, true><<<g1, 256, GT_SMEM>>>(p_attn, p_wo,
        bo, nullptr, nullptr, x, p_x2, nullptr, nullptr, nullptr, M_ROWS, Ee, Ee);

    // h = LN2(x2)
    ln_kernel<<<M_ROWS / 8, 256>>>(p_x2, ln2_w, ln2_b, p_h);

    // fc = gelu(h @ w_fc + b_fc)  (fp16 out)
    transpose_h_kernel<<<dim3(FF/32, Ee/32), 256>>>(w_fc, p_wfc, Ee, FF);
    dim3 g2(FF / 128, M_ROWS / 128);
    gemm_h<2, false><<<g2, 256, GT_SMEM>>>(p_h, p_wfc,
        b_fc, nullptr, nullptr, nullptr, nullptr, p_fc, nullptr, nullptr, M_ROWS, FF, Ee);

    // out = x2 + fc @ w_proj + b_proj
    transpose_h_kernel<<<dim3(Ee/32, FF/32), 256>>>(w_proj, p_wpj, FF, Ee);
    gemm_h<0, true><<<g1, 256, GT_SMEM>>>(p_fc, p_wpj,
        b_proj, nullptr, nullptr, p_x2, out, nullptr, nullptr, nullptr, M_ROWS, Ee, FF);
}